// round 5
// baseline (speedup 1.0000x reference)
#include <cuda_runtime.h>
#include <cuda_bf16.h>
#include <cfloat>
#include <math.h>
#include <cstdint>

#define T_TOK   2048
#define D_DIM   768
#define H_HEADS 4
#define N_KEYS  25600
#define KD      128
#define KNN     16
#define HID_A   44
#define HID_S   1024
#define QDIM    (H_HEADS*KD)   // 512
#define BN_EPS  1e-5f

#define KEY_SPLITS 2
#define KEYS_PER_SPLIT (N_KEYS / KEY_SPLITS)   // 12800
#define CHUNK_N 128
#define NCHUNK (KEYS_PER_SPLIT / CHUNK_N)      // 100
#define TOK_TILE 128
#define LISTCAP 24
#define NCAND  (KEY_SPLITS * 2 * LISTCAP)      // 96 candidates per (token, head)

// ---------------- scratch (device globals; no allocations allowed) ----------
__device__ __nv_bfloat16 g_qhi[T_TOK * QDIM];
__device__ float g_qf[T_TOK * QDIM];
__device__ __nv_bfloat16 g_khi[H_HEADS * N_KEYS * KD];
__device__ int   g_ptopi[T_TOK * H_HEADS * NCAND];
__device__ int   g_topidx[T_TOK * H_HEADS * KNN];
__device__ float g_gates[T_TOK * H_HEADS * KNN];
__device__ float g_comb[T_TOK];
__device__ float g_hid[T_TOK * HID_S];

// ============================================================================
// helpers
// ============================================================================
__device__ __forceinline__ uint32_t smem_u32(const void* p) {
    uint32_t a;
    asm("{ .reg .u64 t; cvta.to.shared.u64 t, %1; cvt.u32.u64 %0, t; }" : "=r"(a) : "l"(p));
    return a;
}
#define CP_ASYNC16(dst, src) \
    asm volatile("cp.async.cg.shared.global [%0], [%1], 16;" :: "r"((uint32_t)(dst)), "l"(src))
#define CP_COMMIT() asm volatile("cp.async.commit_group;" ::: "memory")
#define CP_WAIT0()  asm volatile("cp.async.wait_group 0;" ::: "memory")

__device__ __forceinline__ void ldmx4(uint32_t& r0, uint32_t& r1, uint32_t& r2, uint32_t& r3,
                                      uint32_t addr) {
    asm volatile("ldmatrix.sync.aligned.m8n8.x4.shared.b16 {%0,%1,%2,%3}, [%4];"
                 : "=r"(r0), "=r"(r1), "=r"(r2), "=r"(r3) : "r"(addr));
}
__device__ __forceinline__ void mma_bf16(float* c, const uint32_t* a, const uint32_t* b) {
    asm volatile(
        "mma.sync.aligned.m16n8k16.row.col.f32.bf16.bf16.f32 "
        "{%0,%1,%2,%3}, {%4,%5,%6,%7}, {%8,%9}, {%0,%1,%2,%3};"
        : "+f"(c[0]), "+f"(c[1]), "+f"(c[2]), "+f"(c[3])
        : "r"(a[0]), "r"(a[1]), "r"(a[2]), "r"(a[3]), "r"(b[0]), "r"(b[1]));
}

// ============================================================================
// keysprep: fp32 keys -> bf16 hi
// ============================================================================
__global__ void keysprep_kernel(const float* __restrict__ keys)
{
    size_t i = (size_t)blockIdx.x * 256 + threadIdx.x;      // 4 elems each
    const float4 v = ((const float4*)keys)[i];
    ((__nv_bfloat162*)g_khi)[2 * i] =
        __nv_bfloat162(__float2bfloat16(v.x), __float2bfloat16(v.y));
    ((__nv_bfloat162*)g_khi)[2 * i + 1] =
        __nv_bfloat162(__float2bfloat16(v.z), __float2bfloat16(v.w));
}

// ============================================================================
// Kernel 1: q = BN(x @ wq^T + bq) -> g_qhi (bf16) + g_qf (fp32)
// 128x64 tile, 256 threads, 8x4 micro-tile
// ============================================================================
__global__ void __launch_bounds__(256) qproj_kernel(
    const float* __restrict__ x,  const float* __restrict__ wq,
    const float* __restrict__ bq, const float* __restrict__ gamma,
    const float* __restrict__ beta, const float* __restrict__ mean,
    const float* __restrict__ var)
{
    __shared__ float sA[16][130];
    __shared__ float sB[16][66];
    const int m0 = blockIdx.x * 128;
    const int n0 = blockIdx.y * 64;
    const int tid = threadIdx.x;
    const int kk = tid & 15, rr = tid >> 4;
    const int ty = tid >> 4, tx = tid & 15;

    float acc[8][4] = {};
    for (int k0 = 0; k0 < D_DIM; k0 += 16) {
#pragma unroll
        for (int s = 0; s < 8; ++s)
            sA[kk][rr + 16 * s] = x[(size_t)(m0 + rr + 16 * s) * D_DIM + k0 + kk];
#pragma unroll
        for (int s = 0; s < 4; ++s)
            sB[kk][rr + 16 * s] = wq[(size_t)(n0 + rr + 16 * s) * D_DIM + k0 + kk];
        __syncthreads();
#pragma unroll
        for (int k = 0; k < 16; ++k) {
            float a[8], b[4];
#pragma unroll
            for (int i = 0; i < 8; ++i) a[i] = sA[k][ty + 16 * i];
#pragma unroll
            for (int j = 0; j < 4; ++j) b[j] = sB[k][tx + 16 * j];
#pragma unroll
            for (int i = 0; i < 8; ++i)
#pragma unroll
                for (int j = 0; j < 4; ++j) acc[i][j] = fmaf(a[i], b[j], acc[i][j]);
        }
        __syncthreads();
    }
#pragma unroll
    for (int i = 0; i < 8; ++i)
#pragma unroll
        for (int j = 0; j < 4; ++j) {
            int m = m0 + ty + 16 * i;
            int n = n0 + tx + 16 * j;
            float v = acc[i][j] + bq[n];
            v = (v - mean[n]) * rsqrtf(var[n] + BN_EPS) * gamma[n] + beta[n];
            g_qf[(size_t)m * QDIM + n] = v;
            g_qhi[(size_t)m * QDIM + n] = __float2bfloat16(v);
        }
}

// ============================================================================
// Kernel 2: pass-1 scores via bf16-hi mma.sync + top-24 candidate lists.
// 256 threads (8 warps 2x4). 128 tokens x 128-key chunks. Double-buffered B.
// ============================================================================
#define AB_STRIDE 272
#define SMS_A     0            // 128*272 = 34816
#define SMS_B0    34816
#define SMS_B1    69632
#define SMS_S     104448       // float[128][132] = 67584
#define SMS_TV    172032       // float[256*24]
#define SMS_TI    196608       // int[256*24]
#define SMS_TOTAL 221184
#define S_STRIDE  132

__global__ void __launch_bounds__(256, 1) scores_mma_kernel()
{
    extern __shared__ char smem[];
    const uint32_t smb = smem_u32(smem);
    const int tid  = threadIdx.x;
    const int wid  = tid >> 5;
    const int lane = tid & 31;

    const int t0 = blockIdx.x * TOK_TILE;
    const int h  = blockIdx.y;
    const int z  = blockIdx.z;
    const int keybase = z * KEYS_PER_SPLIT;

    const int warp_m = wid >> 2;
    const int warp_n = wid & 3;

    // per-thread staging offsets
    uint32_t bdst[8], bsrc[8];
#pragma unroll
    for (int i = 0; i < 8; ++i) {
        int idx = tid + i * 256;
        int r = idx >> 4, seg = idx & 15;
        bdst[i] = (uint32_t)(r * AB_STRIDE + seg * 16);
        bsrc[i] = (uint32_t)(r * 256 + seg * 16);
    }

    // stage A (q hi) + first B chunk
    {
        const char* qh = (const char*)(g_qhi + (size_t)t0 * QDIM + h * KD);
#pragma unroll
        for (int i = 0; i < 8; ++i) {
            int idx = tid + i * 256;
            int r = idx >> 4, seg = idx & 15;
            CP_ASYNC16(smb + SMS_A + bdst[i], qh + (size_t)r * (QDIM * 2) + seg * 16);
        }
    }
    const char* khbase = (const char*)(g_khi + ((size_t)h * N_KEYS + keybase) * KD);
    {
#pragma unroll
        for (int i = 0; i < 8; ++i) CP_ASYNC16(smb + SMS_B0 + bdst[i], khbase + bsrc[i]);
        CP_COMMIT();
    }

    // candidate lists (per thread = per (token, parity))
    float* tv = (float*)(smem + SMS_TV) + tid * LISTCAP;
    int*   ti = (int*)(smem + SMS_TI)   + tid * LISTCAP;
#pragma unroll
    for (int k = 0; k < LISTCAP; ++k) tv[k] = -FLT_MAX;
    float minv = -FLT_MAX;

    const uint32_t a_row_off = (uint32_t)((warp_m * 64 + (lane & 15)) * AB_STRIDE + (lane >> 4) * 16);
    const uint32_t b_row_off = (uint32_t)((warp_n * 32 + (lane & 7) + ((lane >> 4) << 3)) * AB_STRIDE
                                          + ((lane >> 3) & 1) * 16);

    float* sS = (float*)(smem + SMS_S);
    const int s_token = tid >> 1;
    const int s_par   = tid & 1;

    for (int c = 0; c < NCHUNK; ++c) {
        const uint32_t bbase = (c & 1) ? (smb + SMS_B1) : (smb + SMS_B0);
        CP_WAIT0();
        __syncthreads();          // B(c) visible; previous scan done

        // prefetch next chunk into the other buffer (overlaps MMA + epilogue)
        if (c + 1 < NCHUNK) {
            const uint32_t obase = (c & 1) ? (smb + SMS_B0) : (smb + SMS_B1);
            const uint32_t cb = (uint32_t)((c + 1) * CHUNK_N * KD * 2);
#pragma unroll
            for (int i = 0; i < 8; ++i) CP_ASYNC16(obase + bdst[i], khbase + cb + bsrc[i]);
            CP_COMMIT();
        }

        float C[4][4][4];
#pragma unroll
        for (int i = 0; i < 4; ++i)
#pragma unroll
            for (int j = 0; j < 4; ++j)
#pragma unroll
                for (int e = 0; e < 4; ++e) C[i][j][e] = 0.f;

#pragma unroll
        for (int ks = 0; ks < 8; ++ks) {
            const uint32_t koff = (uint32_t)(ks * 32);
            uint32_t bh[8];
            ldmx4(bh[0], bh[1], bh[2], bh[3], bbase + b_row_off + koff);
            ldmx4(bh[4], bh[5], bh[6], bh[7], bbase + b_row_off + koff + 16 * AB_STRIDE);
#pragma unroll
            for (int i = 0; i < 4; ++i) {
                uint32_t ah[4];
                ldmx4(ah[0], ah[1], ah[2], ah[3],
                      smb + SMS_A + a_row_off + koff + (uint32_t)(i * 16 * AB_STRIDE));
#pragma unroll
                for (int j = 0; j < 4; ++j) mma_bf16(C[i][j], ah, bh + 2 * j);
            }
        }

        // write scores
        const int trow = lane >> 2;
        const int tcol = (lane & 3) * 2;
#pragma unroll
        for (int i = 0; i < 4; ++i) {
            int tok = warp_m * 64 + i * 16 + trow;
#pragma unroll
            for (int j = 0; j < 4; ++j) {
                int key = warp_n * 32 + j * 8 + tcol;
                *(float2*)(sS + (size_t)tok * S_STRIDE + key)       = make_float2(C[i][j][0], C[i][j][1]);
                *(float2*)(sS + (size_t)(tok + 8) * S_STRIDE + key) = make_float2(C[i][j][2], C[i][j][3]);
            }
        }
        __syncthreads();

        // candidate scan: 2 threads per token, interleaved float4 stripes
        {
            const float4* row = (const float4*)(sS + (size_t)s_token * S_STRIDE);
            const int n0 = keybase + c * CHUNK_N;
#pragma unroll 4
            for (int m = 0; m < 16; ++m) {
                int j4 = 2 * m + s_par;
                float4 v = row[j4];
                int base = n0 + 4 * j4;
#pragma unroll
                for (int e = 0; e < 4; ++e) {
                    float vv = (e == 0) ? v.x : (e == 1) ? v.y : (e == 2) ? v.z : v.w;
                    if (vv > minv) {
                        int p = LISTCAP - 1;
                        while (p > 0 && tv[p - 1] < vv) { tv[p] = tv[p - 1]; ti[p] = ti[p - 1]; --p; }
                        tv[p] = vv; ti[p] = base + e;
                        minv = tv[LISTCAP - 1];
                    }
                }
            }
        }
        // loop-top sync protects sS rewrite + B buffer reuse
    }

    // write candidate index lists
    {
        int t = t0 + s_token;
        size_t pb = ((((size_t)t * H_HEADS + h) * KEY_SPLITS + z) * 2 + s_par) * LISTCAP;
#pragma unroll
        for (int k = 0; k < LISTCAP; ++k) g_ptopi[pb + k] = ti[k];
    }
}

// ============================================================================
// Kernel 2b: exact fp32 rescore of 96 candidates -> top-16 + softmax gates
// ============================================================================
__global__ void __launch_bounds__(NCAND) rescore_kernel(const float* __restrict__ keys)
{
    const int bh = blockIdx.x;            // t*H + h
    const int t = bh >> 2;
    const int h = bh & 3;
    const int tid = threadIdx.x;

    __shared__ float sq[KD];
    __shared__ float sv[NCAND];
    __shared__ int   sidx[NCAND];

    for (int i = tid; i < KD; i += NCAND) sq[i] = g_qf[(size_t)t * QDIM + h * KD + i];
    sidx[tid] = g_ptopi[(size_t)bh * NCAND + tid];
    __syncthreads();

    const int idx = sidx[tid];
    const float4* kr = (const float4*)(keys + ((size_t)h * N_KEYS + idx) * KD);
    float acc = 0.f;
#pragma unroll 8
    for (int d4 = 0; d4 < KD / 4; ++d4) {
        float4 kv = kr[d4];
        acc = fmaf(kv.x, sq[4 * d4 + 0], acc);
        acc = fmaf(kv.y, sq[4 * d4 + 1], acc);
        acc = fmaf(kv.z, sq[4 * d4 + 2], acc);
        acc = fmaf(kv.w, sq[4 * d4 + 3], acc);
    }
    sv[tid] = acc;
    __syncthreads();

    if (tid == 0) {
        float bv[KNN]; int bi[KNN];
#pragma unroll
        for (int k = 0; k < KNN; ++k) bv[k] = -FLT_MAX;
        for (int j = 0; j < NCAND; ++j) {
            float v = sv[j];
            if (v > bv[KNN - 1]) {
                int p = KNN - 1;
                while (p > 0 && bv[p - 1] < v) { bv[p] = bv[p - 1]; bi[p] = bi[p - 1]; --p; }
                bv[p] = v; bi[p] = sidx[j];
            }
        }
        float mx = bv[0], sum = 0.f, e[KNN];
#pragma unroll
        for (int k = 0; k < KNN; ++k) { e[k] = __expf(bv[k] - mx); sum += e[k]; }
        float inv = 1.f / sum;
        size_t base = (size_t)bh * KNN;
#pragma unroll
        for (int k = 0; k < KNN; ++k) { g_gates[base + k] = e[k] * inv; g_topidx[base + k] = bi[k]; }
    }
}

// ============================================================================
// Kernel 3: tiny PEER expert network per token
// ============================================================================
__global__ void moe_small_kernel(const float* __restrict__ x,
                                 const float* __restrict__ wdown,
                                 const float* __restrict__ wup,
                                 const float* __restrict__ aw1,
                                 const float* __restrict__ aw2,
                                 const float* __restrict__ aw3)
{
    __shared__ float s_aw1[HID_A * KNN];
    __shared__ float s_aw3[HID_A * KNN];
    __shared__ float s_aw2[KNN * HID_A];
    __shared__ float s_z[H_HEADS][KNN];
    __shared__ float s_hid[H_HEADS][HID_A];
    __shared__ float s_red[H_HEADS];
    __shared__ float s_wred[4];
    __shared__ float s_xsum;

    const int t = blockIdx.x;
    const int tid = threadIdx.x;
    const int w = tid >> 5;
    const int lane = tid & 31;

    for (int i = tid; i < HID_A * KNN; i += 128) { s_aw1[i] = aw1[i]; s_aw3[i] = aw3[i]; s_aw2[i] = aw2[i]; }

    float ps = 0.f;
    for (int i = tid; i < D_DIM; i += 128) ps += x[(size_t)t * D_DIM + i];
#pragma unroll
    for (int off = 16; off > 0; off >>= 1) ps += __shfl_down_sync(0xffffffffu, ps, off);
    if (lane == 0) s_wred[w] = ps;
    __syncthreads();
    if (tid == 0) s_xsum = s_wred[0] + s_wred[1] + s_wred[2] + s_wred[3];
    __syncthreads();
    const float xsum = s_xsum;

    const size_t gbase = ((size_t)t * H_HEADS + w) * KNN;
    if (lane < KNN)
        s_z[w][lane] = xsum * wdown[g_topidx[gbase + lane]];
    __syncwarp();

    for (int a = lane; a < HID_A; a += 32) {
        float d1 = 0.f, d3 = 0.f;
#pragma unroll
        for (int k = 0; k < KNN; ++k) {
            float zz = s_z[w][k];
            d1 = fmaf(zz, s_aw1[a * KNN + k], d1);
            d3 = fmaf(zz, s_aw3[a * KNN + k], d3);
        }
        float sl = d1 / (1.f + __expf(-d1));
        s_hid[w][a] = sl * d3;
    }
    __syncwarp();

    float part = 0.f;
    if (lane < KNN) {
        float o = 0.f;
#pragma unroll
        for (int a = 0; a < HID_A; ++a) o = fmaf(s_hid[w][a], s_aw2[lane * HID_A + a], o);
        int id = g_topidx[gbase + lane];
        part = o * g_gates[gbase + lane] * wup[id];
    }
#pragma unroll
    for (int off = 16; off > 0; off >>= 1) part += __shfl_down_sync(0xffffffffu, part, off);
    if (lane == 0) s_red[w] = part;
    __syncthreads();
    if (tid == 0) g_comb[t] = s_red[0] + s_red[1] + s_red[2] + s_red[3];
}

// ============================================================================
// Kernel 4: hid = silu(x @ s_w1^T) * (x @ s_w3^T)  (128x64 tile, 8x4 utile)
// ============================================================================
__global__ void __launch_bounds__(256) swiglu_hid_kernel(
    const float* __restrict__ x, const float* __restrict__ w1,
    const float* __restrict__ w3)
{
    __shared__ float sA[16][130];
    __shared__ float sB1[16][66];
    __shared__ float sB3[16][66];
    const int m0 = blockIdx.x * 128;
    const int n0 = blockIdx.y * 64;
    const int tid = threadIdx.x;
    const int kk = tid & 15, rr = tid >> 4;
    const int ty = tid >> 4, tx = tid & 15;

    float acc1[8][4] = {};
    float acc3[8][4] = {};
    for (int k0 = 0; k0 < D_DIM; k0 += 16) {
#pragma unroll
        for (int s = 0; s < 8; ++s)
            sA[kk][rr + 16 * s] = x[(size_t)(m0 + rr + 16 * s) * D_DIM + k0 + kk];
#pragma unroll
        for (int s = 0; s < 4; ++s) {
            sB1[kk][rr + 16 * s] = w1[(size_t)(n0 + rr + 16 * s) * D_DIM + k0 + kk];
            sB3[kk][rr + 16 * s] = w3[(size_t)(n0 + rr + 16 * s) * D_DIM + k0 + kk];
        }
        __syncthreads();
#pragma unroll
        for (int k = 0; k < 16; ++k) {
            float a[8], b1[4], b3[4];
#pragma unroll
            for (int i = 0; i < 8; ++i) a[i] = sA[k][ty + 16 * i];
#pragma unroll
            for (int j = 0; j < 4; ++j) { b1[j] = sB1[k][tx + 16 * j]; b3[j] = sB3[k][tx + 16 * j]; }
#pragma unroll
            for (int i = 0; i < 8; ++i)
#pragma unroll
                for (int j = 0; j < 4; ++j) {
                    acc1[i][j] = fmaf(a[i], b1[j], acc1[i][j]);
                    acc3[i][j] = fmaf(a[i], b3[j], acc3[i][j]);
                }
        }
        __syncthreads();
    }
#pragma unroll
    for (int i = 0; i < 8; ++i)
#pragma unroll
        for (int j = 0; j < 4; ++j) {
            int m = m0 + ty + 16 * i;
            int n = n0 + tx + 16 * j;
            float v1 = acc1[i][j];
            float sl = v1 / (1.f + __expf(-v1));
            g_hid[(size_t)m * HID_S + n] = sl * acc3[i][j];
        }
}

// ============================================================================
// Kernel 5: out = hid @ s_w2^T + comb[t]  (128x64 tile, 8x4 utile)
// ============================================================================
__global__ void __launch_bounds__(256) out_kernel(const float* __restrict__ w2,
                                                  float* __restrict__ out)
{
    __shared__ float sA[16][130];
    __shared__ float sB[16][66];
    const int m0 = blockIdx.x * 128;
    const int n0 = blockIdx.y * 64;
    const int tid = threadIdx.x;
    const int kk = tid & 15, rr = tid >> 4;
    const int ty = tid >> 4, tx = tid & 15;

    float acc[8][4] = {};
    for (int k0 = 0; k0 < HID_S; k0 += 16) {
#pragma unroll
        for (int s = 0; s < 8; ++s)
            sA[kk][rr + 16 * s] = g_hid[(size_t)(m0 + rr + 16 * s) * HID_S + k0 + kk];
#pragma unroll
        for (int s = 0; s < 4; ++s)
            sB[kk][rr + 16 * s] = w2[(size_t)(n0 + rr + 16 * s) * HID_S + k0 + kk];
        __syncthreads();
#pragma unroll
        for (int k = 0; k < 16; ++k) {
            float a[8], b[4];
#pragma unroll
            for (int i = 0; i < 8; ++i) a[i] = sA[k][ty + 16 * i];
#pragma unroll
            for (int j = 0; j < 4; ++j) b[j] = sB[k][tx + 16 * j];
#pragma unroll
            for (int i = 0; i < 8; ++i)
#pragma unroll
                for (int j = 0; j < 4; ++j) acc[i][j] = fmaf(a[i], b[j], acc[i][j]);
        }
        __syncthreads();
    }
#pragma unroll
    for (int i = 0; i < 8; ++i) {
        int m = m0 + ty + 16 * i;
        float c = g_comb[m];
#pragma unroll
        for (int j = 0; j < 4; ++j) {
            int n = n0 + tx + 16 * j;
            out[(size_t)m * D_DIM + n] = acc[i][j] + c;
        }
    }
}

// ============================================================================
extern "C" void kernel_launch(void* const* d_in, const int* in_sizes, int n_in,
                              void* d_out, int out_size)
{
    const float* x        = (const float*)d_in[0];
    const float* wq       = (const float*)d_in[1];
    const float* bq       = (const float*)d_in[2];
    const float* bn_gamma = (const float*)d_in[3];
    const float* bn_beta  = (const float*)d_in[4];
    const float* bn_mean  = (const float*)d_in[5];
    const float* bn_var   = (const float*)d_in[6];
    const float* keys     = (const float*)d_in[7];
    const float* w_down   = (const float*)d_in[8];
    const float* w_up     = (const float*)d_in[9];
    const float* a_w1     = (const float*)d_in[10];
    const float* a_w2     = (const float*)d_in[11];
    const float* a_w3     = (const float*)d_in[12];
    const float* s_w1     = (const float*)d_in[13];
    const float* s_w2     = (const float*)d_in[14];
    const float* s_w3     = (const float*)d_in[15];
    float* out            = (float*)d_out;

    cudaFuncSetAttribute(scores_mma_kernel,
                         cudaFuncAttributeMaxDynamicSharedMemorySize, SMS_TOTAL);

    keysprep_kernel<<<(H_HEADS * N_KEYS * KD) / (256 * 4), 256>>>(keys);
    qproj_kernel<<<dim3(T_TOK / 128, QDIM / 64), 256>>>(x, wq, bq, bn_gamma, bn_beta, bn_mean, bn_var);
    scores_mma_kernel<<<dim3(T_TOK / TOK_TILE, H_HEADS, KEY_SPLITS), 256, SMS_TOTAL>>>();
    rescore_kernel<<<T_TOK * H_HEADS, NCAND>>>(keys);
    moe_small_kernel<<<T_TOK, 128>>>(x, w_down, w_up, a_w1, a_w2, a_w3);
    swiglu_hid_kernel<<<dim3(T_TOK / 128, HID_S / 64), 256>>>(x, s_w1, s_w3);
    out_kernel<<<dim3(T_TOK / 128, D_DIM / 64), 256>>>(s_w2, out);
}

// round 6
// speedup vs baseline: 1.8991x; 1.8991x over previous
#include <cuda_runtime.h>
#include <cuda_bf16.h>
#include <cfloat>
#include <math.h>
#include <cstdint>

#define T_TOK   2048
#define D_DIM   768
#define H_HEADS 4
#define N_KEYS  25600
#define KD      128
#define KNN     16
#define HID_A   44
#define HID_S   1024
#define QDIM    (H_HEADS*KD)   // 512
#define BN_EPS  1e-5f

#define KEY_SPLITS 2
#define KEYS_PER_SPLIT (N_KEYS / KEY_SPLITS)   // 12800
#define CHUNK_N 128
#define NCHUNK (KEYS_PER_SPLIT / CHUNK_N)      // 100
#define TOK_TILE 128
#define NCAND  (KEY_SPLITS * 2 * KNN)          // 64 candidates per (token, head)

// ---------------- scratch (device globals; no allocations allowed) ----------
__device__ __nv_bfloat16 g_qhi[T_TOK * QDIM];
__device__ float g_qf[T_TOK * QDIM];
__device__ __nv_bfloat16 g_khi[H_HEADS * N_KEYS * KD];
__device__ int   g_ptopi[T_TOK * H_HEADS * NCAND];
__device__ int   g_topidx[T_TOK * H_HEADS * KNN];
__device__ float g_gates[T_TOK * H_HEADS * KNN];
__device__ float g_comb[T_TOK];
__device__ float g_hid[T_TOK * HID_S];

// ============================================================================
// helpers
// ============================================================================
__device__ __forceinline__ uint32_t smem_u32(const void* p) {
    uint32_t a;
    asm("{ .reg .u64 t; cvta.to.shared.u64 t, %1; cvt.u32.u64 %0, t; }" : "=r"(a) : "l"(p));
    return a;
}
#define CP_ASYNC16(dst, src) \
    asm volatile("cp.async.cg.shared.global [%0], [%1], 16;" :: "r"((uint32_t)(dst)), "l"(src))
#define CP_COMMIT() asm volatile("cp.async.commit_group;" ::: "memory")
#define CP_WAIT0()  asm volatile("cp.async.wait_group 0;" ::: "memory")

__device__ __forceinline__ void ldmx4(uint32_t& r0, uint32_t& r1, uint32_t& r2, uint32_t& r3,
                                      uint32_t addr) {
    asm volatile("ldmatrix.sync.aligned.m8n8.x4.shared.b16 {%0,%1,%2,%3}, [%4];"
                 : "=r"(r0), "=r"(r1), "=r"(r2), "=r"(r3) : "r"(addr));
}
__device__ __forceinline__ void mma_bf16(float* c, const uint32_t* a, const uint32_t* b) {
    asm volatile(
        "mma.sync.aligned.m16n8k16.row.col.f32.bf16.bf16.f32 "
        "{%0,%1,%2,%3}, {%4,%5,%6,%7}, {%8,%9}, {%0,%1,%2,%3};"
        : "+f"(c[0]), "+f"(c[1]), "+f"(c[2]), "+f"(c[3])
        : "r"(a[0]), "r"(a[1]), "r"(a[2]), "r"(a[3]), "r"(b[0]), "r"(b[1]));
}

// fully unrolled register insertion into sorted-desc list of 16
__device__ __forceinline__ void reg_insert16(float* tv, int* ti, float vv, int idx) {
#pragma unroll
    for (int p = KNN - 1; p > 0; --p) {
        bool shift = tv[p - 1] < vv;
        bool here  = !shift && (tv[p] < vv);
        float ntv = shift ? tv[p - 1] : (here ? vv : tv[p]);
        int   nti = shift ? ti[p - 1] : (here ? idx : ti[p]);
        tv[p] = ntv; ti[p] = nti;
    }
    if (tv[0] < vv) { tv[0] = vv; ti[0] = idx; }
}

// ============================================================================
// keysprep: fp32 keys -> bf16 hi
// ============================================================================
__global__ void keysprep_kernel(const float* __restrict__ keys)
{
    size_t i = (size_t)blockIdx.x * 256 + threadIdx.x;      // 4 elems each
    const float4 v = ((const float4*)keys)[i];
    ((__nv_bfloat162*)g_khi)[2 * i] =
        __nv_bfloat162(__float2bfloat16(v.x), __float2bfloat16(v.y));
    ((__nv_bfloat162*)g_khi)[2 * i + 1] =
        __nv_bfloat162(__float2bfloat16(v.z), __float2bfloat16(v.w));
}

// ============================================================================
// Kernel 1: q = BN(x @ wq^T + bq) -> g_qf (fp32) + g_qhi (bf16)
// 64x64 tile, 256 threads (R4-proven shape)
// ============================================================================
__global__ void qproj_kernel(const float* __restrict__ x,
                             const float* __restrict__ wq,
                             const float* __restrict__ bq,
                             const float* __restrict__ gamma,
                             const float* __restrict__ beta,
                             const float* __restrict__ mean,
                             const float* __restrict__ var)
{
    __shared__ float sA[16][65];
    __shared__ float sB[16][65];
    const int m0 = blockIdx.x * 64;
    const int n0 = blockIdx.y * 64;
    const int tid = threadIdx.x;
    const int kk = tid & 15, r = tid >> 4;
    const int ty = tid >> 4, tx = tid & 15;

    float acc[4][4] = {};
    for (int k0 = 0; k0 < D_DIM; k0 += 16) {
#pragma unroll
        for (int s = 0; s < 4; ++s) {
            sA[kk][r + 16 * s] = x[(size_t)(m0 + r + 16 * s) * D_DIM + k0 + kk];
            sB[kk][r + 16 * s] = wq[(size_t)(n0 + r + 16 * s) * D_DIM + k0 + kk];
        }
        __syncthreads();
#pragma unroll
        for (int k = 0; k < 16; ++k) {
            float a[4], b[4];
#pragma unroll
            for (int i = 0; i < 4; ++i) { a[i] = sA[k][ty + 16 * i]; b[i] = sB[k][tx + 16 * i]; }
#pragma unroll
            for (int i = 0; i < 4; ++i)
#pragma unroll
                for (int j = 0; j < 4; ++j) acc[i][j] = fmaf(a[i], b[j], acc[i][j]);
        }
        __syncthreads();
    }
#pragma unroll
    for (int i = 0; i < 4; ++i)
#pragma unroll
        for (int j = 0; j < 4; ++j) {
            int m = m0 + ty + 16 * i;
            int n = n0 + tx + 16 * j;
            float v = acc[i][j] + bq[n];
            v = (v - mean[n]) * rsqrtf(var[n] + BN_EPS) * gamma[n] + beta[n];
            g_qf[(size_t)m * QDIM + n] = v;
            g_qhi[(size_t)m * QDIM + n] = __float2bfloat16(v);
        }
}

// ============================================================================
// Kernel 2: pass-1 scores, bf16-hi mma.sync, register top-16 candidate lists.
// 256 threads (8 warps 2x4). 128 tokens x 128-key chunks. Double-buffered B.
// ============================================================================
#define AB_STRIDE 272
#define SMS_A     0            // 128*272 = 34816
#define SMS_B0    34816
#define SMS_B1    69632
#define SMS_S     104448       // float[128][132] = 67584
#define SMS_TOTAL 172032
#define S_STRIDE  132

__global__ void __launch_bounds__(256, 1) scores_mma_kernel()
{
    extern __shared__ char smem[];
    const uint32_t smb = smem_u32(smem);
    const int tid  = threadIdx.x;
    const int wid  = tid >> 5;
    const int lane = tid & 31;

    const int t0 = blockIdx.x * TOK_TILE;
    const int h  = blockIdx.y;
    const int z  = blockIdx.z;
    const int keybase = z * KEYS_PER_SPLIT;

    const int warp_m = wid >> 2;
    const int warp_n = wid & 3;

    uint32_t bdst[8], bsrc[8];
#pragma unroll
    for (int i = 0; i < 8; ++i) {
        int idx = tid + i * 256;
        int r = idx >> 4, seg = idx & 15;
        bdst[i] = (uint32_t)(r * AB_STRIDE + seg * 16);
        bsrc[i] = (uint32_t)(r * 256 + seg * 16);
    }

    // stage A (q hi) + first B chunk
    {
        const char* qh = (const char*)(g_qhi + (size_t)t0 * QDIM + h * KD);
#pragma unroll
        for (int i = 0; i < 8; ++i) {
            int idx = tid + i * 256;
            int r = idx >> 4, seg = idx & 15;
            CP_ASYNC16(smb + SMS_A + bdst[i], qh + (size_t)r * (QDIM * 2) + seg * 16);
        }
    }
    const char* khbase = (const char*)(g_khi + ((size_t)h * N_KEYS + keybase) * KD);
    {
#pragma unroll
        for (int i = 0; i < 8; ++i) CP_ASYNC16(smb + SMS_B0 + bdst[i], khbase + bsrc[i]);
        CP_COMMIT();
    }

    // register candidate lists (per thread = (token, parity) stream)
    float tv[KNN]; int ti[KNN];
#pragma unroll
    for (int k = 0; k < KNN; ++k) { tv[k] = -FLT_MAX; ti[k] = 0; }
    float minv = -FLT_MAX;

    const uint32_t a_row_off = (uint32_t)((warp_m * 64 + (lane & 15)) * AB_STRIDE + (lane >> 4) * 16);
    const uint32_t b_row_off = (uint32_t)((warp_n * 32 + (lane & 7) + ((lane >> 4) << 3)) * AB_STRIDE
                                          + ((lane >> 3) & 1) * 16);

    float* sS = (float*)(smem + SMS_S);
    const int s_token = tid >> 1;
    const int s_par   = tid & 1;

    for (int c = 0; c < NCHUNK; ++c) {
        const uint32_t bbase = (c & 1) ? (smb + SMS_B1) : (smb + SMS_B0);
        CP_WAIT0();
        __syncthreads();          // B(c) visible to all; scan of c-1 done by all

        float C[4][4][4];
#pragma unroll
        for (int i = 0; i < 4; ++i)
#pragma unroll
            for (int j = 0; j < 4; ++j)
#pragma unroll
                for (int e = 0; e < 4; ++e) C[i][j][e] = 0.f;

#pragma unroll
        for (int ks = 0; ks < 8; ++ks) {
            const uint32_t koff = (uint32_t)(ks * 32);
            uint32_t bh[8];
            ldmx4(bh[0], bh[1], bh[2], bh[3], bbase + b_row_off + koff);
            ldmx4(bh[4], bh[5], bh[6], bh[7], bbase + b_row_off + koff + 16 * AB_STRIDE);
#pragma unroll
            for (int i = 0; i < 4; ++i) {
                uint32_t ah[4];
                ldmx4(ah[0], ah[1], ah[2], ah[3],
                      smb + SMS_A + a_row_off + koff + (uint32_t)(i * 16 * AB_STRIDE));
#pragma unroll
                for (int j = 0; j < 4; ++j) mma_bf16(C[i][j], ah, bh + 2 * j);
            }
        }

        // prefetch c+1 into the other buffer (its last reader was MMA of c-1,
        // globally complete since the sync at this chunk's top)
        if (c + 1 < NCHUNK) {
            const uint32_t obase = (c & 1) ? (smb + SMS_B0) : (smb + SMS_B1);
            const uint32_t cb = (uint32_t)((c + 1) * CHUNK_N * KD * 2);
#pragma unroll
            for (int i = 0; i < 8; ++i) CP_ASYNC16(obase + bdst[i], khbase + cb + bsrc[i]);
            CP_COMMIT();
        }

        // write scores to sS
        const int trow = lane >> 2;
        const int tcol = (lane & 3) * 2;
#pragma unroll
        for (int i = 0; i < 4; ++i) {
            int tok = warp_m * 64 + i * 16 + trow;
#pragma unroll
            for (int j = 0; j < 4; ++j) {
                int key = warp_n * 32 + j * 8 + tcol;
                *(float2*)(sS + (size_t)tok * S_STRIDE + key)       = make_float2(C[i][j][0], C[i][j][1]);
                *(float2*)(sS + (size_t)(tok + 8) * S_STRIDE + key) = make_float2(C[i][j][2], C[i][j][3]);
            }
        }
        __syncthreads();

        // candidate scan: 2 threads per token, interleaved float4 stripes
        {
            const float4* row = (const float4*)(sS + (size_t)s_token * S_STRIDE);
            const int n0 = keybase + c * CHUNK_N;
#pragma unroll 4
            for (int m = 0; m < 16; ++m) {
                int j4 = 2 * m + s_par;
                float4 v = row[j4];
                int base = n0 + 4 * j4;
                if (v.x > minv) { reg_insert16(tv, ti, v.x, base + 0); minv = tv[KNN - 1]; }
                if (v.y > minv) { reg_insert16(tv, ti, v.y, base + 1); minv = tv[KNN - 1]; }
                if (v.z > minv) { reg_insert16(tv, ti, v.z, base + 2); minv = tv[KNN - 1]; }
                if (v.w > minv) { reg_insert16(tv, ti, v.w, base + 3); minv = tv[KNN - 1]; }
            }
        }
        // next loop-top CP_WAIT0+sync orders sS rewrite after all scans
    }

    // write candidate index lists
    {
        int t = t0 + s_token;
        size_t pb = ((((size_t)t * H_HEADS + h) * KEY_SPLITS + z) * 2 + s_par) * KNN;
#pragma unroll
        for (int k = 0; k < KNN; ++k) g_ptopi[pb + k] = ti[k];
    }
}

// ============================================================================
// Kernel 2b: exact fp32 rescore of 64 candidates -> top-16 + softmax gates
// ============================================================================
__global__ void __launch_bounds__(NCAND) rescore_kernel(const float* __restrict__ keys)
{
    const int bh = blockIdx.x;            // t*H + h
    const int t = bh >> 2;
    const int h = bh & 3;
    const int tid = threadIdx.x;

    __shared__ float sq[KD];
    __shared__ float sv[NCAND];
    __shared__ int   sidx[NCAND];

    for (int i = tid; i < KD; i += NCAND) sq[i] = g_qf[(size_t)t * QDIM + h * KD + i];
    sidx[tid] = g_ptopi[(size_t)bh * NCAND + tid];
    __syncthreads();

    const int idx = sidx[tid];
    const float4* kr = (const float4*)(keys + ((size_t)h * N_KEYS + idx) * KD);
    float acc = 0.f;
#pragma unroll 8
    for (int d4 = 0; d4 < KD / 4; ++d4) {
        float4 kv = kr[d4];
        acc = fmaf(kv.x, sq[4 * d4 + 0], acc);
        acc = fmaf(kv.y, sq[4 * d4 + 1], acc);
        acc = fmaf(kv.z, sq[4 * d4 + 2], acc);
        acc = fmaf(kv.w, sq[4 * d4 + 3], acc);
    }
    sv[tid] = acc;
    __syncthreads();

    if (tid == 0) {
        float bv[KNN]; int bi[KNN];
#pragma unroll
        for (int k = 0; k < KNN; ++k) { bv[k] = -FLT_MAX; bi[k] = 0; }
        for (int j = 0; j < NCAND; ++j) {
            float v = sv[j];
            if (v > bv[KNN - 1]) {
                int p = KNN - 1;
                while (p > 0 && bv[p - 1] < v) { bv[p] = bv[p - 1]; bi[p] = bi[p - 1]; --p; }
                bv[p] = v; bi[p] = sidx[j];
            }
        }
        float mx = bv[0], sum = 0.f, e[KNN];
#pragma unroll
        for (int k = 0; k < KNN; ++k) { e[k] = __expf(bv[k] - mx); sum += e[k]; }
        float inv = 1.f / sum;
        size_t base = (size_t)bh * KNN;
#pragma unroll
        for (int k = 0; k < KNN; ++k) { g_gates[base + k] = e[k] * inv; g_topidx[base + k] = bi[k]; }
    }
}

// ============================================================================
// Kernel 3: tiny PEER expert network per token
// ============================================================================
__global__ void moe_small_kernel(const float* __restrict__ x,
                                 const float* __restrict__ wdown,
                                 const float* __restrict__ wup,
                                 const float* __restrict__ aw1,
                                 const float* __restrict__ aw2,
                                 const float* __restrict__ aw3)
{
    __shared__ float s_aw1[HID_A * KNN];
    __shared__ float s_aw3[HID_A * KNN];
    __shared__ float s_aw2[KNN * HID_A];
    __shared__ float s_z[H_HEADS][KNN];
    __shared__ float s_hid[H_HEADS][HID_A];
    __shared__ float s_red[H_HEADS];
    __shared__ float s_wred[4];
    __shared__ float s_xsum;

    const int t = blockIdx.x;
    const int tid = threadIdx.x;
    const int w = tid >> 5;
    const int lane = tid & 31;

    for (int i = tid; i < HID_A * KNN; i += 128) { s_aw1[i] = aw1[i]; s_aw3[i] = aw3[i]; s_aw2[i] = aw2[i]; }

    float ps = 0.f;
    for (int i = tid; i < D_DIM; i += 128) ps += x[(size_t)t * D_DIM + i];
#pragma unroll
    for (int off = 16; off > 0; off >>= 1) ps += __shfl_down_sync(0xffffffffu, ps, off);
    if (lane == 0) s_wred[w] = ps;
    __syncthreads();
    if (tid == 0) s_xsum = s_wred[0] + s_wred[1] + s_wred[2] + s_wred[3];
    __syncthreads();
    const float xsum = s_xsum;

    const size_t gbase = ((size_t)t * H_HEADS + w) * KNN;
    if (lane < KNN)
        s_z[w][lane] = xsum * wdown[g_topidx[gbase + lane]];
    __syncwarp();

    for (int a = lane; a < HID_A; a += 32) {
        float d1 = 0.f, d3 = 0.f;
#pragma unroll
        for (int k = 0; k < KNN; ++k) {
            float zz = s_z[w][k];
            d1 = fmaf(zz, s_aw1[a * KNN + k], d1);
            d3 = fmaf(zz, s_aw3[a * KNN + k], d3);
        }
        float sl = d1 / (1.f + __expf(-d1));
        s_hid[w][a] = sl * d3;
    }
    __syncwarp();

    float part = 0.f;
    if (lane < KNN) {
        float o = 0.f;
#pragma unroll
        for (int a = 0; a < HID_A; ++a) o = fmaf(s_hid[w][a], s_aw2[lane * HID_A + a], o);
        int id = g_topidx[gbase + lane];
        part = o * g_gates[gbase + lane] * wup[id];
    }
#pragma unroll
    for (int off = 16; off > 0; off >>= 1) part += __shfl_down_sync(0xffffffffu, part, off);
    if (lane == 0) s_red[w] = part;
    __syncthreads();
    if (tid == 0) g_comb[t] = s_red[0] + s_red[1] + s_red[2] + s_red[3];
}

// ============================================================================
// Kernel 4: hid = silu(x @ s_w1^T) * (x @ s_w3^T)  (R4 64x64 proven shape)
// ============================================================================
__global__ void swiglu_hid_kernel(const float* __restrict__ x,
                                  const float* __restrict__ w1,
                                  const float* __restrict__ w3)
{
    __shared__ float sA[16][65];
    __shared__ float sB1[16][65];
    __shared__ float sB3[16][65];
    const int m0 = blockIdx.x * 64;
    const int n0 = blockIdx.y * 64;
    const int tid = threadIdx.x;
    const int kk = tid & 15, r = tid >> 4;
    const int ty = tid >> 4, tx = tid & 15;

    float acc1[4][4] = {};
    float acc3[4][4] = {};
    for (int k0 = 0; k0 < D_DIM; k0 += 16) {
#pragma unroll
        for (int s = 0; s < 4; ++s) {
            sA[kk][r + 16 * s]  = x[(size_t)(m0 + r + 16 * s) * D_DIM + k0 + kk];
            sB1[kk][r + 16 * s] = w1[(size_t)(n0 + r + 16 * s) * D_DIM + k0 + kk];
            sB3[kk][r + 16 * s] = w3[(size_t)(n0 + r + 16 * s) * D_DIM + k0 + kk];
        }
        __syncthreads();
#pragma unroll
        for (int k = 0; k < 16; ++k) {
            float a[4], b1[4], b3[4];
#pragma unroll
            for (int i = 0; i < 4; ++i) {
                a[i]  = sA[k][ty + 16 * i];
                b1[i] = sB1[k][tx + 16 * i];
                b3[i] = sB3[k][tx + 16 * i];
            }
#pragma unroll
            for (int i = 0; i < 4; ++i)
#pragma unroll
                for (int j = 0; j < 4; ++j) {
                    acc1[i][j] = fmaf(a[i], b1[j], acc1[i][j]);
                    acc3[i][j] = fmaf(a[i], b3[j], acc3[i][j]);
                }
        }
        __syncthreads();
    }
#pragma unroll
    for (int i = 0; i < 4; ++i)
#pragma unroll
        for (int j = 0; j < 4; ++j) {
            int m = m0 + ty + 16 * i;
            int n = n0 + tx + 16 * j;
            float v1 = acc1[i][j];
            float sl = v1 / (1.f + __expf(-v1));
            g_hid[(size_t)m * HID_S + n] = sl * acc3[i][j];
        }
}

// ============================================================================
// Kernel 5: out = hid @ s_w2^T + comb[t]  (R4 64x64 proven shape)
// ============================================================================
__global__ void out_kernel(const float* __restrict__ w2, float* __restrict__ out)
{
    __shared__ float sA[16][65];
    __shared__ float sB[16][65];
    const int m0 = blockIdx.x * 64;
    const int n0 = blockIdx.y * 64;
    const int tid = threadIdx.x;
    const int kk = tid & 15, r = tid >> 4;
    const int ty = tid >> 4, tx = tid & 15;

    float acc[4][4] = {};
    for (int k0 = 0; k0 < HID_S; k0 += 16) {
#pragma unroll
        for (int s = 0; s < 4; ++s) {
            sA[kk][r + 16 * s] = g_hid[(size_t)(m0 + r + 16 * s) * HID_S + k0 + kk];
            sB[kk][r + 16 * s] = w2[(size_t)(n0 + r + 16 * s) * HID_S + k0 + kk];
        }
        __syncthreads();
#pragma unroll
        for (int k = 0; k < 16; ++k) {
            float a[4], b[4];
#pragma unroll
            for (int i = 0; i < 4; ++i) { a[i] = sA[k][ty + 16 * i]; b[i] = sB[k][tx + 16 * i]; }
#pragma unroll
            for (int i = 0; i < 4; ++i)
#pragma unroll
                for (int j = 0; j < 4; ++j) acc[i][j] = fmaf(a[i], b[j], acc[i][j]);
        }
        __syncthreads();
    }
#pragma unroll
    for (int i = 0; i < 4; ++i) {
        int m = m0 + ty + 16 * i;
        float c = g_comb[m];
#pragma unroll
        for (int j = 0; j < 4; ++j) {
            int n = n0 + tx + 16 * j;
            out[(size_t)m * D_DIM + n] = acc[i][j] + c;
        }
    }
}

// ============================================================================
extern "C" void kernel_launch(void* const* d_in, const int* in_sizes, int n_in,
                              void* d_out, int out_size)
{
    const float* x        = (const float*)d_in[0];
    const float* wq       = (const float*)d_in[1];
    const float* bq       = (const float*)d_in[2];
    const float* bn_gamma = (const float*)d_in[3];
    const float* bn_beta  = (const float*)d_in[4];
    const float* bn_mean  = (const float*)d_in[5];
    const float* bn_var   = (const float*)d_in[6];
    const float* keys     = (const float*)d_in[7];
    const float* w_down   = (const float*)d_in[8];
    const float* w_up     = (const float*)d_in[9];
    const float* a_w1     = (const float*)d_in[10];
    const float* a_w2     = (const float*)d_in[11];
    const float* a_w3     = (const float*)d_in[12];
    const float* s_w1     = (const float*)d_in[13];
    const float* s_w2     = (const float*)d_in[14];
    const float* s_w3     = (const float*)d_in[15];
    float* out            = (float*)d_out;

    cudaFuncSetAttribute(scores_mma_kernel,
                         cudaFuncAttributeMaxDynamicSharedMemorySize, SMS_TOTAL);

    keysprep_kernel<<<(H_HEADS * N_KEYS * KD) / (256 * 4), 256>>>(keys);
    qproj_kernel<<<dim3(T_TOK / 64, QDIM / 64), 256>>>(x, wq, bq, bn_gamma, bn_beta, bn_mean, bn_var);
    scores_mma_kernel<<<dim3(T_TOK / TOK_TILE, H_HEADS, KEY_SPLITS), 256, SMS_TOTAL>>>();
    rescore_kernel<<<T_TOK * H_HEADS, NCAND>>>(keys);
    moe_small_kernel<<<T_TOK, 128>>>(x, w_down, w_up, a_w1, a_w2, a_w3);
    swiglu_hid_kernel<<<dim3(T_TOK / 64, HID_S / 64), 256>>>(x, s_w1, s_w3);
    out_kernel<<<dim3(T_TOK / 64, D_DIM / 64), 256>>>(s_w2, out);
}

// round 7
// speedup vs baseline: 2.0216x; 1.0645x over previous
#include <cuda_runtime.h>
#include <cuda_bf16.h>
#include <cfloat>
#include <math.h>
#include <cstdint>

#define T_TOK   2048
#define D_DIM   768
#define H_HEADS 4
#define N_KEYS  25600
#define KD      128
#define KNN     16
#define HID_A   44
#define HID_S   1024
#define QDIM    (H_HEADS*KD)   // 512
#define BN_EPS  1e-5f

#define KEY_SPLITS 2
#define KEYS_PER_SPLIT (N_KEYS / KEY_SPLITS)   // 12800
#define CHUNK_N 128
#define NCHUNK (KEYS_PER_SPLIT / CHUNK_N)      // 100
#define TOK_TILE 128
#define NCAND  (KEY_SPLITS * KNN)              // 32 candidates per (token, head)

// ---------------- scratch (device globals; no allocations allowed) ----------
__device__ __nv_bfloat16 g_qhi[T_TOK * QDIM];
__device__ float g_qf[T_TOK * QDIM];
__device__ __nv_bfloat16 g_khi[H_HEADS * N_KEYS * KD];
__device__ int   g_ptopi[T_TOK * H_HEADS * NCAND];
__device__ int   g_topidx[T_TOK * H_HEADS * KNN];
__device__ float g_gates[T_TOK * H_HEADS * KNN];
__device__ float g_comb[T_TOK];
__device__ float g_hid[T_TOK * HID_S];

// ============================================================================
// helpers
// ============================================================================
__device__ __forceinline__ uint32_t smem_u32(const void* p) {
    uint32_t a;
    asm("{ .reg .u64 t; cvta.to.shared.u64 t, %1; cvt.u32.u64 %0, t; }" : "=r"(a) : "l"(p));
    return a;
}
#define CP_ASYNC16(dst, src) \
    asm volatile("cp.async.cg.shared.global [%0], [%1], 16;" :: "r"((uint32_t)(dst)), "l"(src))
#define CP_COMMIT() asm volatile("cp.async.commit_group;" ::: "memory")
#define CP_WAIT0()  asm volatile("cp.async.wait_group 0;" ::: "memory")

__device__ __forceinline__ void ldmx4(uint32_t& r0, uint32_t& r1, uint32_t& r2, uint32_t& r3,
                                      uint32_t addr) {
    asm volatile("ldmatrix.sync.aligned.m8n8.x4.shared.b16 {%0,%1,%2,%3}, [%4];"
                 : "=r"(r0), "=r"(r1), "=r"(r2), "=r"(r3) : "r"(addr));
}
__device__ __forceinline__ void mma_bf16(float* c, const uint32_t* a, const uint32_t* b) {
    asm volatile(
        "mma.sync.aligned.m16n8k16.row.col.f32.bf16.bf16.f32 "
        "{%0,%1,%2,%3}, {%4,%5,%6,%7}, {%8,%9}, {%0,%1,%2,%3};"
        : "+f"(c[0]), "+f"(c[1]), "+f"(c[2]), "+f"(c[3])
        : "r"(a[0]), "r"(a[1]), "r"(a[2]), "r"(a[3]), "r"(b[0]), "r"(b[1]));
}

// fully unrolled register insertion into sorted-desc list of 16
__device__ __forceinline__ void reg_insert16(float* tv, int* ti, float vv, int idx) {
#pragma unroll
    for (int p = KNN - 1; p > 0; --p) {
        bool shift = tv[p - 1] < vv;
        bool here  = !shift && (tv[p] < vv);
        float ntv = shift ? tv[p - 1] : (here ? vv : tv[p]);
        int   nti = shift ? ti[p - 1] : (here ? idx : ti[p]);
        tv[p] = ntv; ti[p] = nti;
    }
    if (tv[0] < vv) { tv[0] = vv; ti[0] = idx; }
}

// ============================================================================
// keysprep: fp32 keys -> bf16 hi
// ============================================================================
__global__ void keysprep_kernel(const float* __restrict__ keys)
{
    size_t i = (size_t)blockIdx.x * 256 + threadIdx.x;      // 4 elems each
    const float4 v = ((const float4*)keys)[i];
    ((__nv_bfloat162*)g_khi)[2 * i] =
        __nv_bfloat162(__float2bfloat16(v.x), __float2bfloat16(v.y));
    ((__nv_bfloat162*)g_khi)[2 * i + 1] =
        __nv_bfloat162(__float2bfloat16(v.z), __float2bfloat16(v.w));
}

// ============================================================================
// Kernel 1: q = BN(x @ wq^T + bq) -> g_qf (fp32) + g_qhi (bf16)
// ============================================================================
__global__ void qproj_kernel(const float* __restrict__ x,
                             const float* __restrict__ wq,
                             const float* __restrict__ bq,
                             const float* __restrict__ gamma,
                             const float* __restrict__ beta,
                             const float* __restrict__ mean,
                             const float* __restrict__ var)
{
    __shared__ float sA[16][65];
    __shared__ float sB[16][65];
    const int m0 = blockIdx.x * 64;
    const int n0 = blockIdx.y * 64;
    const int tid = threadIdx.x;
    const int kk = tid & 15, r = tid >> 4;
    const int ty = tid >> 4, tx = tid & 15;

    float acc[4][4] = {};
    for (int k0 = 0; k0 < D_DIM; k0 += 16) {
#pragma unroll
        for (int s = 0; s < 4; ++s) {
            sA[kk][r + 16 * s] = x[(size_t)(m0 + r + 16 * s) * D_DIM + k0 + kk];
            sB[kk][r + 16 * s] = wq[(size_t)(n0 + r + 16 * s) * D_DIM + k0 + kk];
        }
        __syncthreads();
#pragma unroll
        for (int k = 0; k < 16; ++k) {
            float a[4], b[4];
#pragma unroll
            for (int i = 0; i < 4; ++i) { a[i] = sA[k][ty + 16 * i]; b[i] = sB[k][tx + 16 * i]; }
#pragma unroll
            for (int i = 0; i < 4; ++i)
#pragma unroll
                for (int j = 0; j < 4; ++j) acc[i][j] = fmaf(a[i], b[j], acc[i][j]);
        }
        __syncthreads();
    }
#pragma unroll
    for (int i = 0; i < 4; ++i)
#pragma unroll
        for (int j = 0; j < 4; ++j) {
            int m = m0 + ty + 16 * i;
            int n = n0 + tx + 16 * j;
            float v = acc[i][j] + bq[n];
            v = (v - mean[n]) * rsqrtf(var[n] + BN_EPS) * gamma[n] + beta[n];
            g_qf[(size_t)m * QDIM + n] = v;
            g_qhi[(size_t)m * QDIM + n] = __float2bfloat16(v);
        }
}

// ============================================================================
// Kernel 2: pass-1 scores, bf16-hi mma.sync, register top-16 streams,
// in-kernel 4-way merge -> exact per-(token,split) top-16 candidates.
// 512 threads (16 warps 4x4). 128 tokens x 128-key chunks. Double-buffered B.
// ============================================================================
#define AB_STRIDE 272
#define SMS_A     0            // 128*272 = 34816
#define SMS_B0    34816
#define SMS_B1    69632
#define SMS_S     104448       // float[128][132] = 67584 (also merge scratch)
#define SMS_TOTAL 172032
#define S_STRIDE  132

__global__ void __launch_bounds__(512, 1) scores_mma_kernel()
{
    extern __shared__ char smem[];
    const uint32_t smb = smem_u32(smem);
    const int tid  = threadIdx.x;
    const int wid  = tid >> 5;
    const int lane = tid & 31;

    const int t0 = blockIdx.x * TOK_TILE;
    const int h  = blockIdx.y;
    const int z  = blockIdx.z;
    const int keybase = z * KEYS_PER_SPLIT;

    const int warp_m = wid >> 2;          // 0..3 -> tokens 32*warp_m
    const int warp_n = wid & 3;           // 0..3 -> keys   32*warp_n

    uint32_t bdst[4], bsrc[4];
#pragma unroll
    for (int i = 0; i < 4; ++i) {
        int idx = tid + i * 512;
        int r = idx >> 4, seg = idx & 15;
        bdst[i] = (uint32_t)(r * AB_STRIDE + seg * 16);
        bsrc[i] = (uint32_t)(r * 256 + seg * 16);
    }

    // stage A (q hi) + first B chunk
    {
        const char* qh = (const char*)(g_qhi + (size_t)t0 * QDIM + h * KD);
#pragma unroll
        for (int i = 0; i < 4; ++i) {
            int idx = tid + i * 512;
            int r = idx >> 4, seg = idx & 15;
            CP_ASYNC16(smb + SMS_A + bdst[i], qh + (size_t)r * (QDIM * 2) + seg * 16);
        }
    }
    const char* khbase = (const char*)(g_khi + ((size_t)h * N_KEYS + keybase) * KD);
    {
#pragma unroll
        for (int i = 0; i < 4; ++i) CP_ASYNC16(smb + SMS_B0 + bdst[i], khbase + bsrc[i]);
        CP_COMMIT();
    }

    // register candidate lists (per thread = (token, quarter) stream)
    float tv[KNN]; int ti[KNN];
#pragma unroll
    for (int k = 0; k < KNN; ++k) { tv[k] = -FLT_MAX; ti[k] = 0; }
    float minv = -FLT_MAX;

    const uint32_t a_row_off = (uint32_t)((warp_m * 32 + (lane & 15)) * AB_STRIDE + (lane >> 4) * 16);
    const uint32_t b_row_off = (uint32_t)((warp_n * 32 + (lane & 7) + ((lane >> 4) << 3)) * AB_STRIDE
                                          + ((lane >> 3) & 1) * 16);

    float* sS = (float*)(smem + SMS_S);
    const int s_token = tid >> 2;         // 0..127
    const int s_qtr   = tid & 3;          // 0..3

    for (int c = 0; c < NCHUNK; ++c) {
        const uint32_t bbase = (c & 1) ? (smb + SMS_B1) : (smb + SMS_B0);
        CP_WAIT0();
        __syncthreads();          // B(c) visible; scan of c-1 done by all

        float C[2][4][4];
#pragma unroll
        for (int i = 0; i < 2; ++i)
#pragma unroll
            for (int j = 0; j < 4; ++j)
#pragma unroll
                for (int e = 0; e < 4; ++e) C[i][j][e] = 0.f;

#pragma unroll
        for (int ks = 0; ks < 8; ++ks) {
            const uint32_t koff = (uint32_t)(ks * 32);
            uint32_t bh[8];
            ldmx4(bh[0], bh[1], bh[2], bh[3], bbase + b_row_off + koff);
            ldmx4(bh[4], bh[5], bh[6], bh[7], bbase + b_row_off + koff + 16 * AB_STRIDE);
#pragma unroll
            for (int i = 0; i < 2; ++i) {
                uint32_t ah[4];
                ldmx4(ah[0], ah[1], ah[2], ah[3],
                      smb + SMS_A + a_row_off + koff + (uint32_t)(i * 16 * AB_STRIDE));
#pragma unroll
                for (int j = 0; j < 4; ++j) mma_bf16(C[i][j], ah, bh + 2 * j);
            }
        }

        // prefetch c+1 into other buffer (last reader was MMA of c-1)
        if (c + 1 < NCHUNK) {
            const uint32_t obase = (c & 1) ? (smb + SMS_B0) : (smb + SMS_B1);
            const uint32_t cb = (uint32_t)((c + 1) * CHUNK_N * KD * 2);
#pragma unroll
            for (int i = 0; i < 4; ++i) CP_ASYNC16(obase + bdst[i], khbase + cb + bsrc[i]);
            CP_COMMIT();
        }

        // write scores to sS
        const int trow = lane >> 2;
        const int tcol = (lane & 3) * 2;
#pragma unroll
        for (int i = 0; i < 2; ++i) {
            int tok = warp_m * 32 + i * 16 + trow;
#pragma unroll
            for (int j = 0; j < 4; ++j) {
                int key = warp_n * 32 + j * 8 + tcol;
                *(float2*)(sS + (size_t)tok * S_STRIDE + key)       = make_float2(C[i][j][0], C[i][j][1]);
                *(float2*)(sS + (size_t)(tok + 8) * S_STRIDE + key) = make_float2(C[i][j][2], C[i][j][3]);
            }
        }
        __syncthreads();

        // candidate scan: 4 threads per token, interleaved float4 stripes
        {
            const float4* row = (const float4*)(sS + (size_t)s_token * S_STRIDE);
            const int n0 = keybase + c * CHUNK_N;
#pragma unroll 4
            for (int m = 0; m < 8; ++m) {
                int j4 = 4 * m + s_qtr;
                float4 v = row[j4];
                int base = n0 + 4 * j4;
                if (v.x > minv) { reg_insert16(tv, ti, v.x, base + 0); minv = tv[KNN - 1]; }
                if (v.y > minv) { reg_insert16(tv, ti, v.y, base + 1); minv = tv[KNN - 1]; }
                if (v.z > minv) { reg_insert16(tv, ti, v.z, base + 2); minv = tv[KNN - 1]; }
                if (v.w > minv) { reg_insert16(tv, ti, v.w, base + 3); minv = tv[KNN - 1]; }
            }
        }
        // loop-top CP_WAIT0+sync orders sS rewrite after all scans
    }
    __syncthreads();    // final scans done; sS free as merge scratch

    // dump 4 streams per token into smem: token block = 128 floats
    {
        float* mv = sS;
        int*   mi = (int*)sS;
#pragma unroll
        for (int k = 0; k < KNN; ++k) {
            mv[s_token * 128 + s_qtr * KNN + k]      = tv[k];
            mi[s_token * 128 + 64 + s_qtr * KNN + k] = ti[k];
        }
    }
    __syncthreads();

    // merge 64 -> exact top-16 per token, write candidate indices
    if (tid < TOK_TILE) {
        const float* mv = sS + (size_t)tid * 128;
        const int*   mi = (const int*)sS + (size_t)tid * 128 + 64;
        float bv[KNN]; int bi[KNN];
#pragma unroll
        for (int k = 0; k < KNN; ++k) { bv[k] = -FLT_MAX; bi[k] = 0; }
        float mn = -FLT_MAX;
#pragma unroll 4
        for (int j = 0; j < 64; ++j) {
            float v = mv[j];
            if (v > mn) { reg_insert16(bv, bi, v, mi[j]); mn = bv[KNN - 1]; }
        }
        size_t pb = (((size_t)(t0 + tid) * H_HEADS + h) * KEY_SPLITS + z) * KNN;
#pragma unroll
        for (int k = 0; k < KNN; ++k) g_ptopi[pb + k] = bi[k];
    }
}

// ============================================================================
// Kernel 2b: exact fp32 rescore of 32 candidates -> top-16 + softmax gates.
// 1 block per token, 1 warp per head, 1 lane per candidate. Warp-parallel
// rank selection (no serial tail).
// ============================================================================
__global__ void __launch_bounds__(128) rescore_kernel(const float* __restrict__ keys)
{
    const int t = blockIdx.x;
    const int h = threadIdx.x >> 5;
    const int lane = threadIdx.x & 31;
    const int bh = t * H_HEADS + h;

    __shared__ float sq[H_HEADS][KD];

    // warp loads its q row
    *(float4*)(&sq[h][lane * 4]) = *(const float4*)(g_qf + (size_t)t * QDIM + h * KD + lane * 4);
    __syncwarp();

    const int idx = g_ptopi[(size_t)bh * NCAND + lane];
    const float4* kr = (const float4*)(keys + ((size_t)h * N_KEYS + idx) * KD);
    float acc = 0.f;
#pragma unroll
    for (int d4 = 0; d4 < KD / 4; ++d4) {
        float4 kv = kr[d4];
        acc = fmaf(kv.x, sq[h][4 * d4 + 0], acc);
        acc = fmaf(kv.y, sq[h][4 * d4 + 1], acc);
        acc = fmaf(kv.z, sq[h][4 * d4 + 2], acc);
        acc = fmaf(kv.w, sq[h][4 * d4 + 3], acc);
    }

    // rank = #{j : v_j > v_i, tie-break by lane}
    int rank = 0;
#pragma unroll
    for (int j = 0; j < 32; ++j) {
        float vj = __shfl_sync(0xffffffffu, acc, j);
        rank += (vj > acc) || (vj == acc && j < lane);
    }

    // max over top-16 == max over all
    float vmax = acc;
#pragma unroll
    for (int off = 16; off > 0; off >>= 1)
        vmax = fmaxf(vmax, __shfl_xor_sync(0xffffffffu, vmax, off));

    float e = (rank < KNN) ? __expf(acc - vmax) : 0.f;
    float sum = e;
#pragma unroll
    for (int off = 16; off > 0; off >>= 1)
        sum += __shfl_xor_sync(0xffffffffu, sum, off);

    if (rank < KNN) {
        g_gates[(size_t)bh * KNN + rank]  = e / sum;
        g_topidx[(size_t)bh * KNN + rank] = idx;
    }
}

// ============================================================================
// Kernel 3: tiny PEER expert network per token
// ============================================================================
__global__ void moe_small_kernel(const float* __restrict__ x,
                                 const float* __restrict__ wdown,
                                 const float* __restrict__ wup,
                                 const float* __restrict__ aw1,
                                 const float* __restrict__ aw2,
                                 const float* __restrict__ aw3)
{
    __shared__ float s_aw1[HID_A * KNN];
    __shared__ float s_aw3[HID_A * KNN];
    __shared__ float s_aw2[KNN * HID_A];
    __shared__ float s_z[H_HEADS][KNN];
    __shared__ float s_hid[H_HEADS][HID_A];
    __shared__ float s_red[H_HEADS];
    __shared__ float s_wred[4];
    __shared__ float s_xsum;

    const int t = blockIdx.x;
    const int tid = threadIdx.x;
    const int w = tid >> 5;
    const int lane = tid & 31;

    for (int i = tid; i < HID_A * KNN; i += 128) { s_aw1[i] = aw1[i]; s_aw3[i] = aw3[i]; s_aw2[i] = aw2[i]; }

    float ps = 0.f;
    for (int i = tid; i < D_DIM; i += 128) ps += x[(size_t)t * D_DIM + i];
#pragma unroll
    for (int off = 16; off > 0; off >>= 1) ps += __shfl_down_sync(0xffffffffu, ps, off);
    if (lane == 0) s_wred[w] = ps;
    __syncthreads();
    if (tid == 0) s_xsum = s_wred[0] + s_wred[1] + s_wred[2] + s_wred[3];
    __syncthreads();
    const float xsum = s_xsum;

    const size_t gbase = ((size_t)t * H_HEADS + w) * KNN;
    if (lane < KNN)
        s_z[w][lane] = xsum * wdown[g_topidx[gbase + lane]];
    __syncwarp();

    for (int a = lane; a < HID_A; a += 32) {
        float d1 = 0.f, d3 = 0.f;
#pragma unroll
        for (int k = 0; k < KNN; ++k) {
            float zz = s_z[w][k];
            d1 = fmaf(zz, s_aw1[a * KNN + k], d1);
            d3 = fmaf(zz, s_aw3[a * KNN + k], d3);
        }
        float sl = d1 / (1.f + __expf(-d1));
        s_hid[w][a] = sl * d3;
    }
    __syncwarp();

    float part = 0.f;
    if (lane < KNN) {
        float o = 0.f;
#pragma unroll
        for (int a = 0; a < HID_A; ++a) o = fmaf(s_hid[w][a], s_aw2[lane * HID_A + a], o);
        int id = g_topidx[gbase + lane];
        part = o * g_gates[gbase + lane] * wup[id];
    }
#pragma unroll
    for (int off = 16; off > 0; off >>= 1) part += __shfl_down_sync(0xffffffffu, part, off);
    if (lane == 0) s_red[w] = part;
    __syncthreads();
    if (tid == 0) g_comb[t] = s_red[0] + s_red[1] + s_red[2] + s_red[3];
}

// ============================================================================
// Kernel 4: hid = silu(x @ s_w1^T) * (x @ s_w3^T)
// ============================================================================
__global__ void swiglu_hid_kernel(const float* __restrict__ x,
                                  const float* __restrict__ w1,
                                  const float* __restrict__ w3)
{
    __shared__ float sA[16][65];
    __shared__ float sB1[16][65];
    __shared__ float sB3[16][65];
    const int m0 = blockIdx.x * 64;
    const int n0 = blockIdx.y * 64;
    const int tid = threadIdx.x;
    const int kk = tid & 15, r = tid >> 4;
    const int ty = tid >> 4, tx = tid & 15;

    float acc1[4][4] = {};
    float acc3[4][4] = {};
    for (int k0 = 0; k0 < D_DIM; k0 += 16) {
#pragma unroll
        for (int s = 0; s < 4; ++s) {
            sA[kk][r + 16 * s]  = x[(size_t)(m0 + r + 16 * s) * D_DIM + k0 + kk];
            sB1[kk][r + 16 * s] = w1[(size_t)(n0 + r + 16 * s) * D_DIM + k0 + kk];
            sB3[kk][r + 16 * s] = w3[(size_t)(n0 + r + 16 * s) * D_DIM + k0 + kk];
        }
        __syncthreads();
#pragma unroll
        for (int k = 0; k < 16; ++k) {
            float a[4], b1[4], b3[4];
#pragma unroll
            for (int i = 0; i < 4; ++i) {
                a[i]  = sA[k][ty + 16 * i];
                b1[i] = sB1[k][tx + 16 * i];
                b3[i] = sB3[k][tx + 16 * i];
            }
#pragma unroll
            for (int i = 0; i < 4; ++i)
#pragma unroll
                for (int j = 0; j < 4; ++j) {
                    acc1[i][j] = fmaf(a[i], b1[j], acc1[i][j]);
                    acc3[i][j] = fmaf(a[i], b3[j], acc3[i][j]);
                }
        }
        __syncthreads();
    }
#pragma unroll
    for (int i = 0; i < 4; ++i)
#pragma unroll
        for (int j = 0; j < 4; ++j) {
            int m = m0 + ty + 16 * i;
            int n = n0 + tx + 16 * j;
            float v1 = acc1[i][j];
            float sl = v1 / (1.f + __expf(-v1));
            g_hid[(size_t)m * HID_S + n] = sl * acc3[i][j];
        }
}

// ============================================================================
// Kernel 5: out = hid @ s_w2^T + comb[t]
// ============================================================================
__global__ void out_kernel(const float* __restrict__ w2, float* __restrict__ out)
{
    __shared__ float sA[16][65];
    __shared__ float sB[16][65];
    const int m0 = blockIdx.x * 64;
    const int n0 = blockIdx.y * 64;
    const int tid = threadIdx.x;
    const int kk = tid & 15, r = tid >> 4;
    const int ty = tid >> 4, tx = tid & 15;

    float acc[4][4] = {};
    for (int k0 = 0; k0 < HID_S; k0 += 16) {
#pragma unroll
        for (int s = 0; s < 4; ++s) {
            sA[kk][r + 16 * s] = g_hid[(size_t)(m0 + r + 16 * s) * HID_S + k0 + kk];
            sB[kk][r + 16 * s] = w2[(size_t)(n0 + r + 16 * s) * HID_S + k0 + kk];
        }
        __syncthreads();
#pragma unroll
        for (int k = 0; k < 16; ++k) {
            float a[4], b[4];
#pragma unroll
            for (int i = 0; i < 4; ++i) { a[i] = sA[k][ty + 16 * i]; b[i] = sB[k][tx + 16 * i]; }
#pragma unroll
            for (int i = 0; i < 4; ++i)
#pragma unroll
                for (int j = 0; j < 4; ++j) acc[i][j] = fmaf(a[i], b[j], acc[i][j]);
        }
        __syncthreads();
    }
#pragma unroll
    for (int i = 0; i < 4; ++i) {
        int m = m0 + ty + 16 * i;
        float c = g_comb[m];
#pragma unroll
        for (int j = 0; j < 4; ++j) {
            int n = n0 + tx + 16 * j;
            out[(size_t)m * D_DIM + n] = acc[i][j] + c;
        }
    }
}

// ============================================================================
extern "C" void kernel_launch(void* const* d_in, const int* in_sizes, int n_in,
                              void* d_out, int out_size)
{
    const float* x        = (const float*)d_in[0];
    const float* wq       = (const float*)d_in[1];
    const float* bq       = (const float*)d_in[2];
    const float* bn_gamma = (const float*)d_in[3];
    const float* bn_beta  = (const float*)d_in[4];
    const float* bn_mean  = (const float*)d_in[5];
    const float* bn_var   = (const float*)d_in[6];
    const float* keys     = (const float*)d_in[7];
    const float* w_down   = (const float*)d_in[8];
    const float* w_up     = (const float*)d_in[9];
    const float* a_w1     = (const float*)d_in[10];
    const float* a_w2     = (const float*)d_in[11];
    const float* a_w3     = (const float*)d_in[12];
    const float* s_w1     = (const float*)d_in[13];
    const float* s_w2     = (const float*)d_in[14];
    const float* s_w3     = (const float*)d_in[15];
    float* out            = (float*)d_out;

    cudaFuncSetAttribute(scores_mma_kernel,
                         cudaFuncAttributeMaxDynamicSharedMemorySize, SMS_TOTAL);

    keysprep_kernel<<<(H_HEADS * N_KEYS * KD) / (256 * 4), 256>>>(keys);
    qproj_kernel<<<dim3(T_TOK / 64, QDIM / 64), 256>>>(x, wq, bq, bn_gamma, bn_beta, bn_mean, bn_var);
    scores_mma_kernel<<<dim3(T_TOK / TOK_TILE, H_HEADS, KEY_SPLITS), 512, SMS_TOTAL>>>();
    rescore_kernel<<<T_TOK, 128>>>(keys);
    moe_small_kernel<<<T_TOK, 128>>>(x, w_down, w_up, a_w1, a_w2, a_w3);
    swiglu_hid_kernel<<<dim3(T_TOK / 64, HID_S / 64), 256>>>(x, s_w1, s_w3);
    out_kernel<<<dim3(T_TOK / 64, D_DIM / 64), 256>>>(s_w2, out);
}

// round 8
// speedup vs baseline: 2.5780x; 1.2752x over previous
#include <cuda_runtime.h>
#include <cuda_bf16.h>
#include <cfloat>
#include <math.h>
#include <cstdint>

#define T_TOK   2048
#define D_DIM   768
#define H_HEADS 4
#define N_KEYS  25600
#define KD      128
#define KNN     16
#define HID_A   44
#define HID_S   1024
#define QDIM    (H_HEADS*KD)   // 512
#define BN_EPS  1e-5f

#define KEY_SPLITS 2
#define KEYS_PER_SPLIT (N_KEYS / KEY_SPLITS)   // 12800
#define CHUNK_N 128
#define NCHUNK (KEYS_PER_SPLIT / CHUNK_N)      // 100
#define TOK_TILE 128
#define NCAND  (KEY_SPLITS * KNN)              // 32 candidates per (token, head)

// ---------------- scratch (device globals; no allocations allowed) ----------
__device__ __nv_bfloat16 g_qhi[T_TOK * QDIM];
__device__ float g_qf[T_TOK * QDIM];
__device__ __nv_bfloat16 g_khi[H_HEADS * N_KEYS * KD];
__device__ int   g_ptopi[T_TOK * H_HEADS * NCAND];
__device__ int   g_topidx[T_TOK * H_HEADS * KNN];
__device__ float g_gates[T_TOK * H_HEADS * KNN];
__device__ float g_comb[T_TOK];
// bf16 hi/lo operand splits for dense MLP
__device__ __nv_bfloat16 g_xhi[T_TOK * D_DIM];
__device__ __nv_bfloat16 g_xlo[T_TOK * D_DIM];
__device__ __nv_bfloat16 g_w1hi[HID_S * D_DIM];
__device__ __nv_bfloat16 g_w1lo[HID_S * D_DIM];
__device__ __nv_bfloat16 g_w3hi[HID_S * D_DIM];
__device__ __nv_bfloat16 g_w3lo[HID_S * D_DIM];
__device__ __nv_bfloat16 g_w2hi[D_DIM * HID_S];
__device__ __nv_bfloat16 g_w2lo[D_DIM * HID_S];
__device__ __nv_bfloat16 g_hidhi[T_TOK * HID_S];
__device__ __nv_bfloat16 g_hidlo[T_TOK * HID_S];

// ============================================================================
// helpers
// ============================================================================
__device__ __forceinline__ uint32_t smem_u32(const void* p) {
    uint32_t a;
    asm("{ .reg .u64 t; cvta.to.shared.u64 t, %1; cvt.u32.u64 %0, t; }" : "=r"(a) : "l"(p));
    return a;
}
#define CP_ASYNC16(dst, src) \
    asm volatile("cp.async.cg.shared.global [%0], [%1], 16;" :: "r"((uint32_t)(dst)), "l"(src))
#define CP_COMMIT() asm volatile("cp.async.commit_group;" ::: "memory")
#define CP_WAIT0()  asm volatile("cp.async.wait_group 0;" ::: "memory")

__device__ __forceinline__ void ldmx4(uint32_t& r0, uint32_t& r1, uint32_t& r2, uint32_t& r3,
                                      uint32_t addr) {
    asm volatile("ldmatrix.sync.aligned.m8n8.x4.shared.b16 {%0,%1,%2,%3}, [%4];"
                 : "=r"(r0), "=r"(r1), "=r"(r2), "=r"(r3) : "r"(addr));
}
__device__ __forceinline__ void mma_bf16(float* c, const uint32_t* a, const uint32_t* b) {
    asm volatile(
        "mma.sync.aligned.m16n8k16.row.col.f32.bf16.bf16.f32 "
        "{%0,%1,%2,%3}, {%4,%5,%6,%7}, {%8,%9}, {%0,%1,%2,%3};"
        : "+f"(c[0]), "+f"(c[1]), "+f"(c[2]), "+f"(c[3])
        : "r"(a[0]), "r"(a[1]), "r"(a[2]), "r"(a[3]), "r"(b[0]), "r"(b[1]));
}

// fully unrolled register insertion into sorted-desc list of 16
__device__ __forceinline__ void reg_insert16(float* tv, int* ti, float vv, int idx) {
#pragma unroll
    for (int p = KNN - 1; p > 0; --p) {
        bool shift = tv[p - 1] < vv;
        bool here  = !shift && (tv[p] < vv);
        float ntv = shift ? tv[p - 1] : (here ? vv : tv[p]);
        int   nti = shift ? ti[p - 1] : (here ? idx : ti[p]);
        tv[p] = ntv; ti[p] = nti;
    }
    if (tv[0] < vv) { tv[0] = vv; ti[0] = idx; }
}

// ============================================================================
// keysprep: fp32 keys -> bf16 hi
// ============================================================================
__global__ void keysprep_kernel(const float* __restrict__ keys)
{
    size_t i = (size_t)blockIdx.x * 256 + threadIdx.x;
    const float4 v = ((const float4*)keys)[i];
    ((__nv_bfloat162*)g_khi)[2 * i] =
        __nv_bfloat162(__float2bfloat16(v.x), __float2bfloat16(v.y));
    ((__nv_bfloat162*)g_khi)[2 * i + 1] =
        __nv_bfloat162(__float2bfloat16(v.z), __float2bfloat16(v.w));
}

// ============================================================================
// split: fp32 -> bf16 hi + lo residual
// ============================================================================
__global__ void split_kernel(const float* __restrict__ src,
                             __nv_bfloat16* __restrict__ hi,
                             __nv_bfloat16* __restrict__ lo, int n4)
{
    int i = blockIdx.x * 256 + threadIdx.x;
    if (i >= n4) return;
    float4 v = ((const float4*)src)[i];
    float f[4] = {v.x, v.y, v.z, v.w};
    __nv_bfloat16 h[4], l[4];
#pragma unroll
    for (int k = 0; k < 4; ++k) {
        h[k] = __float2bfloat16(f[k]);
        l[k] = __float2bfloat16(f[k] - __bfloat162float(h[k]));
    }
    ((__nv_bfloat162*)hi)[2 * i]     = __nv_bfloat162(h[0], h[1]);
    ((__nv_bfloat162*)hi)[2 * i + 1] = __nv_bfloat162(h[2], h[3]);
    ((__nv_bfloat162*)lo)[2 * i]     = __nv_bfloat162(l[0], l[1]);
    ((__nv_bfloat162*)lo)[2 * i + 1] = __nv_bfloat162(l[2], l[3]);
}

// ============================================================================
// Kernel 1: q = BN(x @ wq^T + bq) -> g_qf (fp32) + g_qhi (bf16)
// ============================================================================
__global__ void qproj_kernel(const float* __restrict__ x,
                             const float* __restrict__ wq,
                             const float* __restrict__ bq,
                             const float* __restrict__ gamma,
                             const float* __restrict__ beta,
                             const float* __restrict__ mean,
                             const float* __restrict__ var)
{
    __shared__ float sA[16][65];
    __shared__ float sB[16][65];
    const int m0 = blockIdx.x * 64;
    const int n0 = blockIdx.y * 64;
    const int tid = threadIdx.x;
    const int kk = tid & 15, r = tid >> 4;
    const int ty = tid >> 4, tx = tid & 15;

    float acc[4][4] = {};
    for (int k0 = 0; k0 < D_DIM; k0 += 16) {
#pragma unroll
        for (int s = 0; s < 4; ++s) {
            sA[kk][r + 16 * s] = x[(size_t)(m0 + r + 16 * s) * D_DIM + k0 + kk];
            sB[kk][r + 16 * s] = wq[(size_t)(n0 + r + 16 * s) * D_DIM + k0 + kk];
        }
        __syncthreads();
#pragma unroll
        for (int k = 0; k < 16; ++k) {
            float a[4], b[4];
#pragma unroll
            for (int i = 0; i < 4; ++i) { a[i] = sA[k][ty + 16 * i]; b[i] = sB[k][tx + 16 * i]; }
#pragma unroll
            for (int i = 0; i < 4; ++i)
#pragma unroll
                for (int j = 0; j < 4; ++j) acc[i][j] = fmaf(a[i], b[j], acc[i][j]);
        }
        __syncthreads();
    }
#pragma unroll
    for (int i = 0; i < 4; ++i)
#pragma unroll
        for (int j = 0; j < 4; ++j) {
            int m = m0 + ty + 16 * i;
            int n = n0 + tx + 16 * j;
            float v = acc[i][j] + bq[n];
            v = (v - mean[n]) * rsqrtf(var[n] + BN_EPS) * gamma[n] + beta[n];
            g_qf[(size_t)m * QDIM + n] = v;
            g_qhi[(size_t)m * QDIM + n] = __float2bfloat16(v);
        }
}

// ============================================================================
// Kernel 2: pass-1 scores (bf16-hi HMMA) + register top-16 + 4-way merge
// (unchanged from R7)
// ============================================================================
#define AB_STRIDE 272
#define SMS_A     0
#define SMS_B0    34816
#define SMS_B1    69632
#define SMS_S     104448
#define SMS_TOTAL 172032
#define S_STRIDE  132

__global__ void __launch_bounds__(512, 1) scores_mma_kernel()
{
    extern __shared__ char smem[];
    const uint32_t smb = smem_u32(smem);
    const int tid  = threadIdx.x;
    const int wid  = tid >> 5;
    const int lane = tid & 31;

    const int t0 = blockIdx.x * TOK_TILE;
    const int h  = blockIdx.y;
    const int z  = blockIdx.z;
    const int keybase = z * KEYS_PER_SPLIT;

    const int warp_m = wid >> 2;
    const int warp_n = wid & 3;

    uint32_t bdst[4], bsrc[4];
#pragma unroll
    for (int i = 0; i < 4; ++i) {
        int idx = tid + i * 512;
        int r = idx >> 4, seg = idx & 15;
        bdst[i] = (uint32_t)(r * AB_STRIDE + seg * 16);
        bsrc[i] = (uint32_t)(r * 256 + seg * 16);
    }

    {
        const char* qh = (const char*)(g_qhi + (size_t)t0 * QDIM + h * KD);
#pragma unroll
        for (int i = 0; i < 4; ++i) {
            int idx = tid + i * 512;
            int r = idx >> 4, seg = idx & 15;
            CP_ASYNC16(smb + SMS_A + bdst[i], qh + (size_t)r * (QDIM * 2) + seg * 16);
        }
    }
    const char* khbase = (const char*)(g_khi + ((size_t)h * N_KEYS + keybase) * KD);
    {
#pragma unroll
        for (int i = 0; i < 4; ++i) CP_ASYNC16(smb + SMS_B0 + bdst[i], khbase + bsrc[i]);
        CP_COMMIT();
    }

    float tv[KNN]; int ti[KNN];
#pragma unroll
    for (int k = 0; k < KNN; ++k) { tv[k] = -FLT_MAX; ti[k] = 0; }
    float minv = -FLT_MAX;

    const uint32_t a_row_off = (uint32_t)((warp_m * 32 + (lane & 15)) * AB_STRIDE + (lane >> 4) * 16);
    const uint32_t b_row_off = (uint32_t)((warp_n * 32 + (lane & 7) + ((lane >> 4) << 3)) * AB_STRIDE
                                          + ((lane >> 3) & 1) * 16);

    float* sS = (float*)(smem + SMS_S);
    const int s_token = tid >> 2;
    const int s_qtr   = tid & 3;

    for (int c = 0; c < NCHUNK; ++c) {
        const uint32_t bbase = (c & 1) ? (smb + SMS_B1) : (smb + SMS_B0);
        CP_WAIT0();
        __syncthreads();

        float C[2][4][4];
#pragma unroll
        for (int i = 0; i < 2; ++i)
#pragma unroll
            for (int j = 0; j < 4; ++j)
#pragma unroll
                for (int e = 0; e < 4; ++e) C[i][j][e] = 0.f;

#pragma unroll
        for (int ks = 0; ks < 8; ++ks) {
            const uint32_t koff = (uint32_t)(ks * 32);
            uint32_t bh[8];
            ldmx4(bh[0], bh[1], bh[2], bh[3], bbase + b_row_off + koff);
            ldmx4(bh[4], bh[5], bh[6], bh[7], bbase + b_row_off + koff + 16 * AB_STRIDE);
#pragma unroll
            for (int i = 0; i < 2; ++i) {
                uint32_t ah[4];
                ldmx4(ah[0], ah[1], ah[2], ah[3],
                      smb + SMS_A + a_row_off + koff + (uint32_t)(i * 16 * AB_STRIDE));
#pragma unroll
                for (int j = 0; j < 4; ++j) mma_bf16(C[i][j], ah, bh + 2 * j);
            }
        }

        if (c + 1 < NCHUNK) {
            const uint32_t obase = (c & 1) ? (smb + SMS_B0) : (smb + SMS_B1);
            const uint32_t cb = (uint32_t)((c + 1) * CHUNK_N * KD * 2);
#pragma unroll
            for (int i = 0; i < 4; ++i) CP_ASYNC16(obase + bdst[i], khbase + cb + bsrc[i]);
            CP_COMMIT();
        }

        const int trow = lane >> 2;
        const int tcol = (lane & 3) * 2;
#pragma unroll
        for (int i = 0; i < 2; ++i) {
            int tok = warp_m * 32 + i * 16 + trow;
#pragma unroll
            for (int j = 0; j < 4; ++j) {
                int key = warp_n * 32 + j * 8 + tcol;
                *(float2*)(sS + (size_t)tok * S_STRIDE + key)       = make_float2(C[i][j][0], C[i][j][1]);
                *(float2*)(sS + (size_t)(tok + 8) * S_STRIDE + key) = make_float2(C[i][j][2], C[i][j][3]);
            }
        }
        __syncthreads();

        {
            const float4* row = (const float4*)(sS + (size_t)s_token * S_STRIDE);
            const int n0 = keybase + c * CHUNK_N;
#pragma unroll 4
            for (int m = 0; m < 8; ++m) {
                int j4 = 4 * m + s_qtr;
                float4 v = row[j4];
                int base = n0 + 4 * j4;
                if (v.x > minv) { reg_insert16(tv, ti, v.x, base + 0); minv = tv[KNN - 1]; }
                if (v.y > minv) { reg_insert16(tv, ti, v.y, base + 1); minv = tv[KNN - 1]; }
                if (v.z > minv) { reg_insert16(tv, ti, v.z, base + 2); minv = tv[KNN - 1]; }
                if (v.w > minv) { reg_insert16(tv, ti, v.w, base + 3); minv = tv[KNN - 1]; }
            }
        }
    }
    __syncthreads();

    {
        float* mv = sS;
        int*   mi = (int*)sS;
#pragma unroll
        for (int k = 0; k < KNN; ++k) {
            mv[s_token * 128 + s_qtr * KNN + k]      = tv[k];
            mi[s_token * 128 + 64 + s_qtr * KNN + k] = ti[k];
        }
    }
    __syncthreads();

    if (tid < TOK_TILE) {
        const float* mv = sS + (size_t)tid * 128;
        const int*   mi = (const int*)sS + (size_t)tid * 128 + 64;
        float bv[KNN]; int bi[KNN];
#pragma unroll
        for (int k = 0; k < KNN; ++k) { bv[k] = -FLT_MAX; bi[k] = 0; }
        float mn = -FLT_MAX;
#pragma unroll 4
        for (int j = 0; j < 64; ++j) {
            float v = mv[j];
            if (v > mn) { reg_insert16(bv, bi, v, mi[j]); mn = bv[KNN - 1]; }
        }
        size_t pb = (((size_t)(t0 + tid) * H_HEADS + h) * KEY_SPLITS + z) * KNN;
#pragma unroll
        for (int k = 0; k < KNN; ++k) g_ptopi[pb + k] = bi[k];
    }
}

// ============================================================================
// Kernel 2b: exact fp32 rescore (unchanged from R7)
// ============================================================================
__global__ void __launch_bounds__(128) rescore_kernel(const float* __restrict__ keys)
{
    const int t = blockIdx.x;
    const int h = threadIdx.x >> 5;
    const int lane = threadIdx.x & 31;
    const int bh = t * H_HEADS + h;

    __shared__ float sq[H_HEADS][KD];
    *(float4*)(&sq[h][lane * 4]) = *(const float4*)(g_qf + (size_t)t * QDIM + h * KD + lane * 4);
    __syncwarp();

    const int idx = g_ptopi[(size_t)bh * NCAND + lane];
    const float4* kr = (const float4*)(keys + ((size_t)h * N_KEYS + idx) * KD);
    float acc = 0.f;
#pragma unroll
    for (int d4 = 0; d4 < KD / 4; ++d4) {
        float4 kv = kr[d4];
        acc = fmaf(kv.x, sq[h][4 * d4 + 0], acc);
        acc = fmaf(kv.y, sq[h][4 * d4 + 1], acc);
        acc = fmaf(kv.z, sq[h][4 * d4 + 2], acc);
        acc = fmaf(kv.w, sq[h][4 * d4 + 3], acc);
    }

    int rank = 0;
#pragma unroll
    for (int j = 0; j < 32; ++j) {
        float vj = __shfl_sync(0xffffffffu, acc, j);
        rank += (vj > acc) || (vj == acc && j < lane);
    }
    float vmax = acc;
#pragma unroll
    for (int off = 16; off > 0; off >>= 1)
        vmax = fmaxf(vmax, __shfl_xor_sync(0xffffffffu, vmax, off));
    float e = (rank < KNN) ? __expf(acc - vmax) : 0.f;
    float sum = e;
#pragma unroll
    for (int off = 16; off > 0; off >>= 1)
        sum += __shfl_xor_sync(0xffffffffu, sum, off);
    if (rank < KNN) {
        g_gates[(size_t)bh * KNN + rank]  = e / sum;
        g_topidx[(size_t)bh * KNN + rank] = idx;
    }
}

// ============================================================================
// Kernel 3: tiny PEER expert network per token (unchanged)
// ============================================================================
__global__ void moe_small_kernel(const float* __restrict__ x,
                                 const float* __restrict__ wdown,
                                 const float* __restrict__ wup,
                                 const float* __restrict__ aw1,
                                 const float* __restrict__ aw2,
                                 const float* __restrict__ aw3)
{
    __shared__ float s_aw1[HID_A * KNN];
    __shared__ float s_aw3[HID_A * KNN];
    __shared__ float s_aw2[KNN * HID_A];
    __shared__ float s_z[H_HEADS][KNN];
    __shared__ float s_hid[H_HEADS][HID_A];
    __shared__ float s_red[H_HEADS];
    __shared__ float s_wred[4];
    __shared__ float s_xsum;

    const int t = blockIdx.x;
    const int tid = threadIdx.x;
    const int w = tid >> 5;
    const int lane = tid & 31;

    for (int i = tid; i < HID_A * KNN; i += 128) { s_aw1[i] = aw1[i]; s_aw3[i] = aw3[i]; s_aw2[i] = aw2[i]; }

    float ps = 0.f;
    for (int i = tid; i < D_DIM; i += 128) ps += x[(size_t)t * D_DIM + i];
#pragma unroll
    for (int off = 16; off > 0; off >>= 1) ps += __shfl_down_sync(0xffffffffu, ps, off);
    if (lane == 0) s_wred[w] = ps;
    __syncthreads();
    if (tid == 0) s_xsum = s_wred[0] + s_wred[1] + s_wred[2] + s_wred[3];
    __syncthreads();
    const float xsum = s_xsum;

    const size_t gbase = ((size_t)t * H_HEADS + w) * KNN;
    if (lane < KNN)
        s_z[w][lane] = xsum * wdown[g_topidx[gbase + lane]];
    __syncwarp();

    for (int a = lane; a < HID_A; a += 32) {
        float d1 = 0.f, d3 = 0.f;
#pragma unroll
        for (int k = 0; k < KNN; ++k) {
            float zz = s_z[w][k];
            d1 = fmaf(zz, s_aw1[a * KNN + k], d1);
            d3 = fmaf(zz, s_aw3[a * KNN + k], d3);
        }
        float sl = d1 / (1.f + __expf(-d1));
        s_hid[w][a] = sl * d3;
    }
    __syncwarp();

    float part = 0.f;
    if (lane < KNN) {
        float o = 0.f;
#pragma unroll
        for (int a = 0; a < HID_A; ++a) o = fmaf(s_hid[w][a], s_aw2[lane * HID_A + a], o);
        int id = g_topidx[gbase + lane];
        part = o * g_gates[gbase + lane] * wup[id];
    }
#pragma unroll
    for (int off = 16; off > 0; off >>= 1) part += __shfl_down_sync(0xffffffffu, part, off);
    if (lane == 0) s_red[w] = part;
    __syncthreads();
    if (tid == 0) g_comb[t] = s_red[0] + s_red[1] + s_red[2] + s_red[3];
}

// ============================================================================
// Kernel 4: swiglu via HMMA 3-term split.
// C tile 128 tokens x 64 hid-cols; B = {w1,w3} rows n0..n0+63 hi/lo.
// 256 threads = 8 warps (4 m x 2 n), warp tile 32x32, K chunks of 128.
// ============================================================================
#define DW_AH 0            // 128*272 = 34816
#define DW_AL 34816
#define DW_B  69632        // 4 matrices x 64*272=17408: [w1hi][w1lo][w3hi][w3lo]
#define DW_BSZ 17408
#define DW_TOTAL (DW_B + 4*DW_BSZ)   // 139264

__global__ void __launch_bounds__(256, 1) swiglu_mma_kernel()
{
    extern __shared__ char smem[];
    const uint32_t smb = smem_u32(smem);
    const int tid  = threadIdx.x;
    const int wid  = tid >> 5;
    const int lane = tid & 31;
    const int m0 = blockIdx.x * 128;
    const int n0 = blockIdx.y * 64;

    const int warp_m = wid >> 1;   // 0..3
    const int warp_n = wid & 1;    // 0..1

    const uint32_t a_row_off = (uint32_t)((warp_m * 32 + (lane & 15)) * AB_STRIDE + (lane >> 4) * 16);
    const uint32_t b_row_off = (uint32_t)((warp_n * 32 + (lane & 7) + ((lane >> 4) << 3)) * AB_STRIDE
                                          + ((lane >> 3) & 1) * 16);

    float C1[2][4][4] = {};
    float C3[2][4][4] = {};

    const char* axh = (const char*)(g_xhi + (size_t)m0 * D_DIM);
    const char* axl = (const char*)(g_xlo + (size_t)m0 * D_DIM);
    const char* b1h = (const char*)(g_w1hi + (size_t)n0 * D_DIM);
    const char* b1l = (const char*)(g_w1lo + (size_t)n0 * D_DIM);
    const char* b3h = (const char*)(g_w3hi + (size_t)n0 * D_DIM);
    const char* b3l = (const char*)(g_w3lo + (size_t)n0 * D_DIM);

    for (int kc = 0; kc < D_DIM / 128; ++kc) {
        if (kc) __syncthreads();                 // previous MMA done with smem
        const uint32_t ko = (uint32_t)(kc * 256);    // byte offset in K
        // stage A hi/lo (128 rows x 16 segs)
#pragma unroll
        for (int it = 0; it < 8; ++it) {
            int idx = tid + it * 256;
            int r = idx >> 4, seg = idx & 15;
            uint32_t d = (uint32_t)(r * AB_STRIDE + seg * 16);
            uint32_t s = (uint32_t)(r * (D_DIM * 2)) + ko + seg * 16;
            CP_ASYNC16(smb + DW_AH + d, axh + s);
            CP_ASYNC16(smb + DW_AL + d, axl + s);
        }
        // stage 4 B matrices (64 rows x 16 segs each)
#pragma unroll
        for (int it = 0; it < 4; ++it) {
            int idx = tid + it * 256;
            int r = idx >> 4, seg = idx & 15;
            uint32_t d = (uint32_t)(r * AB_STRIDE + seg * 16);
            uint32_t s = (uint32_t)(r * (D_DIM * 2)) + ko + seg * 16;
            CP_ASYNC16(smb + DW_B + 0 * DW_BSZ + d, b1h + s);
            CP_ASYNC16(smb + DW_B + 1 * DW_BSZ + d, b1l + s);
            CP_ASYNC16(smb + DW_B + 2 * DW_BSZ + d, b3h + s);
            CP_ASYNC16(smb + DW_B + 3 * DW_BSZ + d, b3l + s);
        }
        CP_COMMIT(); CP_WAIT0();
        __syncthreads();

#pragma unroll
        for (int ks = 0; ks < 8; ++ks) {
            const uint32_t koff = (uint32_t)(ks * 32);
            uint32_t b1H[8], b1L[8], b3H[8], b3L[8];
            ldmx4(b1H[0], b1H[1], b1H[2], b1H[3], smb + DW_B + 0 * DW_BSZ + b_row_off + koff);
            ldmx4(b1H[4], b1H[5], b1H[6], b1H[7], smb + DW_B + 0 * DW_BSZ + b_row_off + koff + 16 * AB_STRIDE);
            ldmx4(b1L[0], b1L[1], b1L[2], b1L[3], smb + DW_B + 1 * DW_BSZ + b_row_off + koff);
            ldmx4(b1L[4], b1L[5], b1L[6], b1L[7], smb + DW_B + 1 * DW_BSZ + b_row_off + koff + 16 * AB_STRIDE);
            ldmx4(b3H[0], b3H[1], b3H[2], b3H[3], smb + DW_B + 2 * DW_BSZ + b_row_off + koff);
            ldmx4(b3H[4], b3H[5], b3H[6], b3H[7], smb + DW_B + 2 * DW_BSZ + b_row_off + koff + 16 * AB_STRIDE);
            ldmx4(b3L[0], b3L[1], b3L[2], b3L[3], smb + DW_B + 3 * DW_BSZ + b_row_off + koff);
            ldmx4(b3L[4], b3L[5], b3L[6], b3L[7], smb + DW_B + 3 * DW_BSZ + b_row_off + koff + 16 * AB_STRIDE);
#pragma unroll
            for (int i = 0; i < 2; ++i) {
                uint32_t ah[4], al[4];
                ldmx4(ah[0], ah[1], ah[2], ah[3],
                      smb + DW_AH + a_row_off + koff + (uint32_t)(i * 16 * AB_STRIDE));
                ldmx4(al[0], al[1], al[2], al[3],
                      smb + DW_AL + a_row_off + koff + (uint32_t)(i * 16 * AB_STRIDE));
#pragma unroll
                for (int j = 0; j < 4; ++j) {
                    mma_bf16(C1[i][j], ah, b1H + 2 * j);
                    mma_bf16(C1[i][j], ah, b1L + 2 * j);
                    mma_bf16(C1[i][j], al, b1H + 2 * j);
                    mma_bf16(C3[i][j], ah, b3H + 2 * j);
                    mma_bf16(C3[i][j], ah, b3L + 2 * j);
                    mma_bf16(C3[i][j], al, b3H + 2 * j);
                }
            }
        }
    }

    // epilogue: hid = silu(z1)*z3, split to bf16 hi/lo
    const int trow = lane >> 2;
    const int tcol = (lane & 3) * 2;
#pragma unroll
    for (int i = 0; i < 2; ++i) {
#pragma unroll
        for (int j = 0; j < 4; ++j) {
            int n = n0 + warp_n * 32 + j * 8 + tcol;
#pragma unroll
            for (int half = 0; half < 2; ++half) {
                int m = m0 + warp_m * 32 + i * 16 + trow + half * 8;
                float z1a = C1[i][j][2 * half], z1b = C1[i][j][2 * half + 1];
                float z3a = C3[i][j][2 * half], z3b = C3[i][j][2 * half + 1];
                float va = (z1a / (1.f + __expf(-z1a))) * z3a;
                float vb = (z1b / (1.f + __expf(-z1b))) * z3b;
                __nv_bfloat16 ha = __float2bfloat16(va);
                __nv_bfloat16 hb = __float2bfloat16(vb);
                __nv_bfloat16 la = __float2bfloat16(va - __bfloat162float(ha));
                __nv_bfloat16 lb = __float2bfloat16(vb - __bfloat162float(hb));
                *(__nv_bfloat162*)(g_hidhi + (size_t)m * HID_S + n) = __nv_bfloat162(ha, hb);
                *(__nv_bfloat162*)(g_hidlo + (size_t)m * HID_S + n) = __nv_bfloat162(la, lb);
            }
        }
    }
}

// ============================================================================
// Kernel 5: out = hid @ w2^T + comb  via HMMA 3-term split.
// C tile 128 x 64, K=1024 in 8 chunks of 128.
// ============================================================================
#define DO_AH 0
#define DO_AL 34816
#define DO_BH 69632
#define DO_BL (69632 + 17408)
#define DO_TOTAL (69632 + 2*17408)   // 104448

__global__ void __launch_bounds__(256, 1) out_mma_kernel(float* __restrict__ out)
{
    extern __shared__ char smem[];
    const uint32_t smb = smem_u32(smem);
    const int tid  = threadIdx.x;
    const int wid  = tid >> 5;
    const int lane = tid & 31;
    const int m0 = blockIdx.x * 128;
    const int n0 = blockIdx.y * 64;

    const int warp_m = wid >> 1;
    const int warp_n = wid & 1;

    const uint32_t a_row_off = (uint32_t)((warp_m * 32 + (lane & 15)) * AB_STRIDE + (lane >> 4) * 16);
    const uint32_t b_row_off = (uint32_t)((warp_n * 32 + (lane & 7) + ((lane >> 4) << 3)) * AB_STRIDE
                                          + ((lane >> 3) & 1) * 16);

    float C[2][4][4] = {};

    const char* axh = (const char*)(g_hidhi + (size_t)m0 * HID_S);
    const char* axl = (const char*)(g_hidlo + (size_t)m0 * HID_S);
    const char* bh_ = (const char*)(g_w2hi + (size_t)n0 * HID_S);
    const char* bl_ = (const char*)(g_w2lo + (size_t)n0 * HID_S);

    for (int kc = 0; kc < HID_S / 128; ++kc) {
        if (kc) __syncthreads();
        const uint32_t ko = (uint32_t)(kc * 256);
#pragma unroll
        for (int it = 0; it < 8; ++it) {
            int idx = tid + it * 256;
            int r = idx >> 4, seg = idx & 15;
            uint32_t d = (uint32_t)(r * AB_STRIDE + seg * 16);
            uint32_t s = (uint32_t)(r * (HID_S * 2)) + ko + seg * 16;
            CP_ASYNC16(smb + DO_AH + d, axh + s);
            CP_ASYNC16(smb + DO_AL + d, axl + s);
        }
#pragma unroll
        for (int it = 0; it < 4; ++it) {
            int idx = tid + it * 256;
            int r = idx >> 4, seg = idx & 15;
            uint32_t d = (uint32_t)(r * AB_STRIDE + seg * 16);
            uint32_t s = (uint32_t)(r * (HID_S * 2)) + ko + seg * 16;
            CP_ASYNC16(smb + DO_BH + d, bh_ + s);
            CP_ASYNC16(smb + DO_BL + d, bl_ + s);
        }
        CP_COMMIT(); CP_WAIT0();
        __syncthreads();

#pragma unroll
        for (int ks = 0; ks < 8; ++ks) {
            const uint32_t koff = (uint32_t)(ks * 32);
            uint32_t bH[8], bL[8];
            ldmx4(bH[0], bH[1], bH[2], bH[3], smb + DO_BH + b_row_off + koff);
            ldmx4(bH[4], bH[5], bH[6], bH[7], smb + DO_BH + b_row_off + koff + 16 * AB_STRIDE);
            ldmx4(bL[0], bL[1], bL[2], bL[3], smb + DO_BL + b_row_off + koff);
            ldmx4(bL[4], bL[5], bL[6], bL[7], smb + DO_BL + b_row_off + koff + 16 * AB_STRIDE);
#pragma unroll
            for (int i = 0; i < 2; ++i) {
                uint32_t ah[4], al[4];
                ldmx4(ah[0], ah[1], ah[2], ah[3],
                      smb + DO_AH + a_row_off + koff + (uint32_t)(i * 16 * AB_STRIDE));
                ldmx4(al[0], al[1], al[2], al[3],
                      smb + DO_AL + a_row_off + koff + (uint32_t)(i * 16 * AB_STRIDE));
#pragma unroll
                for (int j = 0; j < 4; ++j) {
                    mma_bf16(C[i][j], ah, bH + 2 * j);
                    mma_bf16(C[i][j], ah, bL + 2 * j);
                    mma_bf16(C[i][j], al, bH + 2 * j);
                }
            }
        }
    }

    const int trow = lane >> 2;
    const int tcol = (lane & 3) * 2;
#pragma unroll
    for (int i = 0; i < 2; ++i) {
#pragma unroll
        for (int half = 0; half < 2; ++half) {
            int m = m0 + warp_m * 32 + i * 16 + trow + half * 8;
            float cb = g_comb[m];
#pragma unroll
            for (int j = 0; j < 4; ++j) {
                int n = n0 + warp_n * 32 + j * 8 + tcol;
                *(float2*)(out + (size_t)m * D_DIM + n) =
                    make_float2(C[i][j][2 * half] + cb, C[i][j][2 * half + 1] + cb);
            }
        }
    }
}

// ============================================================================
extern "C" void kernel_launch(void* const* d_in, const int* in_sizes, int n_in,
                              void* d_out, int out_size)
{
    const float* x        = (const float*)d_in[0];
    const float* wq       = (const float*)d_in[1];
    const float* bq       = (const float*)d_in[2];
    const float* bn_gamma = (const float*)d_in[3];
    const float* bn_beta  = (const float*)d_in[4];
    const float* bn_mean  = (const float*)d_in[5];
    const float* bn_var   = (const float*)d_in[6];
    const float* keys     = (const float*)d_in[7];
    const float* w_down   = (const float*)d_in[8];
    const float* w_up     = (const float*)d_in[9];
    const float* a_w1     = (const float*)d_in[10];
    const float* a_w2     = (const float*)d_in[11];
    const float* a_w3     = (const float*)d_in[12];
    const float* s_w1     = (const float*)d_in[13];
    const float* s_w2     = (const float*)d_in[14];
    const float* s_w3     = (const float*)d_in[15];
    float* out            = (float*)d_out;

    __nv_bfloat16 *xhi, *xlo, *w1hi, *w1lo, *w3hi, *w3lo, *w2hi, *w2lo;
    cudaGetSymbolAddress((void**)&xhi, g_xhi);   cudaGetSymbolAddress((void**)&xlo, g_xlo);
    cudaGetSymbolAddress((void**)&w1hi, g_w1hi); cudaGetSymbolAddress((void**)&w1lo, g_w1lo);
    cudaGetSymbolAddress((void**)&w3hi, g_w3hi); cudaGetSymbolAddress((void**)&w3lo, g_w3lo);
    cudaGetSymbolAddress((void**)&w2hi, g_w2hi); cudaGetSymbolAddress((void**)&w2lo, g_w2lo);

    cudaFuncSetAttribute(scores_mma_kernel,
                         cudaFuncAttributeMaxDynamicSharedMemorySize, SMS_TOTAL);
    cudaFuncSetAttribute(swiglu_mma_kernel,
                         cudaFuncAttributeMaxDynamicSharedMemorySize, DW_TOTAL);
    cudaFuncSetAttribute(out_mma_kernel,
                         cudaFuncAttributeMaxDynamicSharedMemorySize, DO_TOTAL);

    keysprep_kernel<<<(H_HEADS * N_KEYS * KD) / (256 * 4), 256>>>(keys);
    split_kernel<<<(T_TOK * D_DIM / 4 + 255) / 256, 256>>>(x, xhi, xlo, T_TOK * D_DIM / 4);
    split_kernel<<<(HID_S * D_DIM / 4 + 255) / 256, 256>>>(s_w1, w1hi, w1lo, HID_S * D_DIM / 4);
    split_kernel<<<(HID_S * D_DIM / 4 + 255) / 256, 256>>>(s_w3, w3hi, w3lo, HID_S * D_DIM / 4);
    split_kernel<<<(D_DIM * HID_S / 4 + 255) / 256, 256>>>(s_w2, w2hi, w2lo, D_DIM * HID_S / 4);
    qproj_kernel<<<dim3(T_TOK / 64, QDIM / 64), 256>>>(x, wq, bq, bn_gamma, bn_beta, bn_mean, bn_var);
    scores_mma_kernel<<<dim3(T_TOK / TOK_TILE, H_HEADS, KEY_SPLITS), 512, SMS_TOTAL>>>();
    rescore_kernel<<<T_TOK, 128>>>(keys);
    moe_small_kernel<<<T_TOK, 128>>>(x, w_down, w_up, a_w1, a_w2, a_w3);
    swiglu_mma_kernel<<<dim3(T_TOK / 128, HID_S / 64), 256, DW_TOTAL>>>();
    out_mma_kernel<<<dim3(T_TOK / 128, D_DIM / 64), 256, DO_TOTAL>>>(out);
}

// round 9
// speedup vs baseline: 2.7279x; 1.0581x over previous
#include <cuda_runtime.h>
#include <cuda_bf16.h>
#include <cfloat>
#include <math.h>
#include <cstdint>

#define T_TOK   2048
#define D_DIM   768
#define H_HEADS 4
#define N_KEYS  25600
#define KD      128
#define KNN     16
#define HID_A   44
#define HID_S   1024
#define QDIM    (H_HEADS*KD)   // 512
#define BN_EPS  1e-5f

#define KEY_SPLITS 4
#define KEYS_PER_SPLIT (N_KEYS / KEY_SPLITS)   // 6400
#define CHUNK_N 64
#define NCHUNK (KEYS_PER_SPLIT / CHUNK_N)      // 100
#define TOK_TILE 128
#define NCAND  (KEY_SPLITS * KNN)              // 64 candidates per (token, head)

// ---------------- scratch (device globals; no allocations allowed) ----------
__device__ __nv_bfloat16 g_qhi[T_TOK * QDIM];
__device__ float g_qf[T_TOK * QDIM];
__device__ __nv_bfloat16 g_khi[H_HEADS * N_KEYS * KD];
__device__ int   g_ptopi[T_TOK * H_HEADS * NCAND];
__device__ int   g_topidx[T_TOK * H_HEADS * KNN];
__device__ float g_gates[T_TOK * H_HEADS * KNN];
__device__ float g_comb[T_TOK];
__device__ float g_bnA[QDIM];
__device__ float g_bnB[QDIM];
// bf16 hi/lo operand splits
__device__ __nv_bfloat16 g_xhi[T_TOK * D_DIM];
__device__ __nv_bfloat16 g_xlo[T_TOK * D_DIM];
__device__ __nv_bfloat16 g_wqhi[QDIM * D_DIM];
__device__ __nv_bfloat16 g_wqlo[QDIM * D_DIM];
__device__ __nv_bfloat16 g_w1hi[HID_S * D_DIM];
__device__ __nv_bfloat16 g_w1lo[HID_S * D_DIM];
__device__ __nv_bfloat16 g_w3hi[HID_S * D_DIM];
__device__ __nv_bfloat16 g_w3lo[HID_S * D_DIM];
__device__ __nv_bfloat16 g_w2hi[D_DIM * HID_S];
__device__ __nv_bfloat16 g_w2lo[D_DIM * HID_S];
__device__ __nv_bfloat16 g_hidhi[T_TOK * HID_S];
__device__ __nv_bfloat16 g_hidlo[T_TOK * HID_S];

// ============================================================================
// helpers
// ============================================================================
__device__ __forceinline__ uint32_t smem_u32(const void* p) {
    uint32_t a;
    asm("{ .reg .u64 t; cvta.to.shared.u64 t, %1; cvt.u32.u64 %0, t; }" : "=r"(a) : "l"(p));
    return a;
}
#define CP_ASYNC16(dst, src) \
    asm volatile("cp.async.cg.shared.global [%0], [%1], 16;" :: "r"((uint32_t)(dst)), "l"(src))
#define CP_COMMIT() asm volatile("cp.async.commit_group;" ::: "memory")
#define CP_WAIT0()  asm volatile("cp.async.wait_group 0;" ::: "memory")

__device__ __forceinline__ void ldmx4(uint32_t& r0, uint32_t& r1, uint32_t& r2, uint32_t& r3,
                                      uint32_t addr) {
    asm volatile("ldmatrix.sync.aligned.m8n8.x4.shared.b16 {%0,%1,%2,%3}, [%4];"
                 : "=r"(r0), "=r"(r1), "=r"(r2), "=r"(r3) : "r"(addr));
}
__device__ __forceinline__ void mma_bf16(float* c, const uint32_t* a, const uint32_t* b) {
    asm volatile(
        "mma.sync.aligned.m16n8k16.row.col.f32.bf16.bf16.f32 "
        "{%0,%1,%2,%3}, {%4,%5,%6,%7}, {%8,%9}, {%0,%1,%2,%3};"
        : "+f"(c[0]), "+f"(c[1]), "+f"(c[2]), "+f"(c[3])
        : "r"(a[0]), "r"(a[1]), "r"(a[2]), "r"(a[3]), "r"(b[0]), "r"(b[1]));
}

// fully unrolled register insertion into sorted-desc list of 16
__device__ __forceinline__ void reg_insert16(float* tv, int* ti, float vv, int idx) {
#pragma unroll
    for (int p = KNN - 1; p > 0; --p) {
        bool shift = tv[p - 1] < vv;
        bool here  = !shift && (tv[p] < vv);
        float ntv = shift ? tv[p - 1] : (here ? vv : tv[p]);
        int   nti = shift ? ti[p - 1] : (here ? idx : ti[p]);
        tv[p] = ntv; ti[p] = nti;
    }
    if (tv[0] < vv) { tv[0] = vv; ti[0] = idx; }
}

// ============================================================================
// keysprep: fp32 keys -> bf16 hi
// ============================================================================
__global__ void keysprep_kernel(const float* __restrict__ keys)
{
    size_t i = (size_t)blockIdx.x * 256 + threadIdx.x;
    const float4 v = ((const float4*)keys)[i];
    ((__nv_bfloat162*)g_khi)[2 * i] =
        __nv_bfloat162(__float2bfloat16(v.x), __float2bfloat16(v.y));
    ((__nv_bfloat162*)g_khi)[2 * i + 1] =
        __nv_bfloat162(__float2bfloat16(v.z), __float2bfloat16(v.w));
}

// ============================================================================
// split: fp32 -> bf16 hi + lo residual
// ============================================================================
__global__ void split_kernel(const float* __restrict__ src,
                             __nv_bfloat16* __restrict__ hi,
                             __nv_bfloat16* __restrict__ lo, int n4)
{
    int i = blockIdx.x * 256 + threadIdx.x;
    if (i >= n4) return;
    float4 v = ((const float4*)src)[i];
    float f[4] = {v.x, v.y, v.z, v.w};
    __nv_bfloat16 h[4], l[4];
#pragma unroll
    for (int k = 0; k < 4; ++k) {
        h[k] = __float2bfloat16(f[k]);
        l[k] = __float2bfloat16(f[k] - __bfloat162float(h[k]));
    }
    ((__nv_bfloat162*)hi)[2 * i]     = __nv_bfloat162(h[0], h[1]);
    ((__nv_bfloat162*)hi)[2 * i + 1] = __nv_bfloat162(h[2], h[3]);
    ((__nv_bfloat162*)lo)[2 * i]     = __nv_bfloat162(l[0], l[1]);
    ((__nv_bfloat162*)lo)[2 * i + 1] = __nv_bfloat162(l[2], l[3]);
}

// ============================================================================
// bnprep: fused BN scale/shift per output column
// ============================================================================
__global__ void bnprep_kernel(const float* __restrict__ bq,
                              const float* __restrict__ gamma,
                              const float* __restrict__ beta,
                              const float* __restrict__ mean,
                              const float* __restrict__ var)
{
    int n = blockIdx.x * 256 + threadIdx.x;
    if (n >= QDIM) return;
    float sc = gamma[n] * rsqrtf(var[n] + BN_EPS);
    g_bnA[n] = sc;
    g_bnB[n] = (bq[n] - mean[n]) * sc + beta[n];
}

// ============================================================================
// shared tile-layout constants
// ============================================================================
#define AB_STRIDE 272

// ============================================================================
// Kernel 1: qproj via HMMA 3-term split. M=2048,N=512,K=768.
// C tile 128 x 64, 256 threads (4m x 2n warps), K chunks of 128.
// epilogue: v = acc*bnA[n]+bnB[n] -> g_qf(fp32)+g_qhi(bf16)
// ============================================================================
#define DO_AH 0
#define DO_AL 34816
#define DO_BH 69632
#define DO_BL (69632 + 17408)
#define DO_TOTAL (69632 + 2*17408)   // 104448

__global__ void __launch_bounds__(256, 2) qproj_mma_kernel()
{
    extern __shared__ char smem[];
    const uint32_t smb = smem_u32(smem);
    const int tid  = threadIdx.x;
    const int wid  = tid >> 5;
    const int lane = tid & 31;
    const int m0 = blockIdx.x * 128;
    const int n0 = blockIdx.y * 64;

    const int warp_m = wid >> 1;
    const int warp_n = wid & 1;

    const uint32_t a_row_off = (uint32_t)((warp_m * 32 + (lane & 15)) * AB_STRIDE + (lane >> 4) * 16);
    const uint32_t b_row_off = (uint32_t)((warp_n * 32 + (lane & 7) + ((lane >> 4) << 3)) * AB_STRIDE
                                          + ((lane >> 3) & 1) * 16);

    float C[2][4][4] = {};

    const char* axh = (const char*)(g_xhi + (size_t)m0 * D_DIM);
    const char* axl = (const char*)(g_xlo + (size_t)m0 * D_DIM);
    const char* bh_ = (const char*)(g_wqhi + (size_t)n0 * D_DIM);
    const char* bl_ = (const char*)(g_wqlo + (size_t)n0 * D_DIM);

    for (int kc = 0; kc < D_DIM / 128; ++kc) {
        if (kc) __syncthreads();
        const uint32_t ko = (uint32_t)(kc * 256);
#pragma unroll
        for (int it = 0; it < 8; ++it) {
            int idx = tid + it * 256;
            int r = idx >> 4, seg = idx & 15;
            uint32_t d = (uint32_t)(r * AB_STRIDE + seg * 16);
            uint32_t s = (uint32_t)(r * (D_DIM * 2)) + ko + seg * 16;
            CP_ASYNC16(smb + DO_AH + d, axh + s);
            CP_ASYNC16(smb + DO_AL + d, axl + s);
        }
#pragma unroll
        for (int it = 0; it < 4; ++it) {
            int idx = tid + it * 256;
            int r = idx >> 4, seg = idx & 15;
            uint32_t d = (uint32_t)(r * AB_STRIDE + seg * 16);
            uint32_t s = (uint32_t)(r * (D_DIM * 2)) + ko + seg * 16;
            CP_ASYNC16(smb + DO_BH + d, bh_ + s);
            CP_ASYNC16(smb + DO_BL + d, bl_ + s);
        }
        CP_COMMIT(); CP_WAIT0();
        __syncthreads();

#pragma unroll
        for (int ks = 0; ks < 8; ++ks) {
            const uint32_t koff = (uint32_t)(ks * 32);
            uint32_t bH[8], bL[8];
            ldmx4(bH[0], bH[1], bH[2], bH[3], smb + DO_BH + b_row_off + koff);
            ldmx4(bH[4], bH[5], bH[6], bH[7], smb + DO_BH + b_row_off + koff + 16 * AB_STRIDE);
            ldmx4(bL[0], bL[1], bL[2], bL[3], smb + DO_BL + b_row_off + koff);
            ldmx4(bL[4], bL[5], bL[6], bL[7], smb + DO_BL + b_row_off + koff + 16 * AB_STRIDE);
#pragma unroll
            for (int i = 0; i < 2; ++i) {
                uint32_t ah[4], al[4];
                ldmx4(ah[0], ah[1], ah[2], ah[3],
                      smb + DO_AH + a_row_off + koff + (uint32_t)(i * 16 * AB_STRIDE));
                ldmx4(al[0], al[1], al[2], al[3],
                      smb + DO_AL + a_row_off + koff + (uint32_t)(i * 16 * AB_STRIDE));
#pragma unroll
                for (int j = 0; j < 4; ++j) {
                    mma_bf16(C[i][j], ah, bH + 2 * j);
                    mma_bf16(C[i][j], ah, bL + 2 * j);
                    mma_bf16(C[i][j], al, bH + 2 * j);
                }
            }
        }
    }

    const int trow = lane >> 2;
    const int tcol = (lane & 3) * 2;
#pragma unroll
    for (int i = 0; i < 2; ++i) {
#pragma unroll
        for (int half = 0; half < 2; ++half) {
            int m = m0 + warp_m * 32 + i * 16 + trow + half * 8;
#pragma unroll
            for (int j = 0; j < 4; ++j) {
                int n = n0 + warp_n * 32 + j * 8 + tcol;
                float va = C[i][j][2 * half]     * g_bnA[n]     + g_bnB[n];
                float vb = C[i][j][2 * half + 1] * g_bnA[n + 1] + g_bnB[n + 1];
                *(float2*)(g_qf + (size_t)m * QDIM + n) = make_float2(va, vb);
                *(__nv_bfloat162*)(g_qhi + (size_t)m * QDIM + n) =
                    __nv_bfloat162(__float2bfloat16(va), __float2bfloat16(vb));
            }
        }
    }
}

// ============================================================================
// Kernel 2: pass-1 scores, bf16-hi HMMA, 2 CTAs/SM for epilogue overlap.
// 256 threads (8 warps 4m x 2n), 128 tokens x 64-key chunks, 100 chunks.
// Register top-16 streams (2/token), shfl pair-merge at end.
// ============================================================================
#define SMS_A     0            // 128*272 = 34816
#define SMS_B0    34816        // 64*272 = 17408
#define SMS_B1    52224
#define SMS_S     69632        // float[128][68] = 34816
#define SMS_TOTAL 104448
#define S_STRIDE  68

__global__ void __launch_bounds__(256, 2) scores_mma_kernel()
{
    extern __shared__ char smem[];
    const uint32_t smb = smem_u32(smem);
    const int tid  = threadIdx.x;
    const int wid  = tid >> 5;
    const int lane = tid & 31;

    const int t0 = blockIdx.x * TOK_TILE;
    const int h  = blockIdx.y;
    const int z  = blockIdx.z;
    const int keybase = z * KEYS_PER_SPLIT;

    const int warp_m = wid >> 1;     // 0..3 -> tokens 32*warp_m
    const int warp_n = wid & 1;      // 0..1 -> keys   32*warp_n

    // B staging: 64 rows x 16 segs = 1024 tasks / 256 thr = 4 each
    uint32_t bdst[4], bsrc[4];
#pragma unroll
    for (int i = 0; i < 4; ++i) {
        int idx = tid + i * 256;
        int r = idx >> 4, seg = idx & 15;
        bdst[i] = (uint32_t)(r * AB_STRIDE + seg * 16);
        bsrc[i] = (uint32_t)(r * 256 + seg * 16);
    }

    // stage A (q hi, 128 rows x 16 segs = 8 each) + first B chunk
    {
        const char* qh = (const char*)(g_qhi + (size_t)t0 * QDIM + h * KD);
#pragma unroll
        for (int i = 0; i < 8; ++i) {
            int idx = tid + i * 256;
            int r = idx >> 4, seg = idx & 15;
            CP_ASYNC16(smb + SMS_A + (uint32_t)(r * AB_STRIDE + seg * 16),
                       qh + (size_t)r * (QDIM * 2) + seg * 16);
        }
    }
    const char* khbase = (const char*)(g_khi + ((size_t)h * N_KEYS + keybase) * KD);
    {
#pragma unroll
        for (int i = 0; i < 4; ++i) CP_ASYNC16(smb + SMS_B0 + bdst[i], khbase + bsrc[i]);
        CP_COMMIT();
    }

    float tv[KNN]; int ti[KNN];
#pragma unroll
    for (int k = 0; k < KNN; ++k) { tv[k] = -FLT_MAX; ti[k] = 0; }
    float minv = -FLT_MAX;

    const uint32_t a_row_off = (uint32_t)((warp_m * 32 + (lane & 15)) * AB_STRIDE + (lane >> 4) * 16);
    const uint32_t b_row_off = (uint32_t)((warp_n * 32 + (lane & 7) + ((lane >> 4) << 3)) * AB_STRIDE
                                          + ((lane >> 3) & 1) * 16);

    float* sS = (float*)(smem + SMS_S);
    const int s_token = tid >> 1;
    const int s_par   = tid & 1;

    for (int c = 0; c < NCHUNK; ++c) {
        const uint32_t bbase = (c & 1) ? (smb + SMS_B1) : (smb + SMS_B0);
        CP_WAIT0();
        __syncthreads();          // B(c) visible; scan of c-1 done by all

        float C[2][4][4];
#pragma unroll
        for (int i = 0; i < 2; ++i)
#pragma unroll
            for (int j = 0; j < 4; ++j)
#pragma unroll
                for (int e = 0; e < 4; ++e) C[i][j][e] = 0.f;

#pragma unroll
        for (int ks = 0; ks < 8; ++ks) {
            const uint32_t koff = (uint32_t)(ks * 32);
            uint32_t bh[8];
            ldmx4(bh[0], bh[1], bh[2], bh[3], bbase + b_row_off + koff);
            ldmx4(bh[4], bh[5], bh[6], bh[7], bbase + b_row_off + koff + 16 * AB_STRIDE);
#pragma unroll
            for (int i = 0; i < 2; ++i) {
                uint32_t ah[4];
                ldmx4(ah[0], ah[1], ah[2], ah[3],
                      smb + SMS_A + a_row_off + koff + (uint32_t)(i * 16 * AB_STRIDE));
#pragma unroll
                for (int j = 0; j < 4; ++j) mma_bf16(C[i][j], ah, bh + 2 * j);
            }
        }

        // prefetch c+1 into the other buffer
        if (c + 1 < NCHUNK) {
            const uint32_t obase = (c & 1) ? (smb + SMS_B0) : (smb + SMS_B1);
            const uint32_t cb = (uint32_t)((c + 1) * CHUNK_N * KD * 2);
#pragma unroll
            for (int i = 0; i < 4; ++i) CP_ASYNC16(obase + bdst[i], khbase + cb + bsrc[i]);
            CP_COMMIT();
        }

        // write scores
        const int trow = lane >> 2;
        const int tcol = (lane & 3) * 2;
#pragma unroll
        for (int i = 0; i < 2; ++i) {
            int tok = warp_m * 32 + i * 16 + trow;
#pragma unroll
            for (int j = 0; j < 4; ++j) {
                int key = warp_n * 32 + j * 8 + tcol;
                *(float2*)(sS + (size_t)tok * S_STRIDE + key)       = make_float2(C[i][j][0], C[i][j][1]);
                *(float2*)(sS + (size_t)(tok + 8) * S_STRIDE + key) = make_float2(C[i][j][2], C[i][j][3]);
            }
        }
        __syncthreads();

        // candidate scan: 2 threads per token, interleaved float4 stripes (8 each)
        {
            const float4* row = (const float4*)(sS + (size_t)s_token * S_STRIDE);
            const int n0 = keybase + c * CHUNK_N;
#pragma unroll 4
            for (int m = 0; m < 8; ++m) {
                int j4 = 2 * m + s_par;
                float4 v = row[j4];
                int base = n0 + 4 * j4;
                if (v.x > minv) { reg_insert16(tv, ti, v.x, base + 0); minv = tv[KNN - 1]; }
                if (v.y > minv) { reg_insert16(tv, ti, v.y, base + 1); minv = tv[KNN - 1]; }
                if (v.z > minv) { reg_insert16(tv, ti, v.z, base + 2); minv = tv[KNN - 1]; }
                if (v.w > minv) { reg_insert16(tv, ti, v.w, base + 3); minv = tv[KNN - 1]; }
            }
        }
    }

    // pair-merge the 2 streams per token via shfl (pairs are adjacent lanes)
    {
        float ov[KNN]; int oi[KNN];
#pragma unroll
        for (int k = 0; k < KNN; ++k) {
            ov[k] = __shfl_down_sync(0xffffffffu, tv[k], 1);
            oi[k] = __shfl_down_sync(0xffffffffu, ti[k], 1);
        }
        if ((tid & 1) == 0) {
#pragma unroll
            for (int k = 0; k < KNN; ++k)
                if (ov[k] > tv[KNN - 1]) reg_insert16(tv, ti, ov[k], oi[k]);
            size_t pb = (((size_t)(t0 + (tid >> 1)) * H_HEADS + h) * KEY_SPLITS + z) * KNN;
#pragma unroll
            for (int k = 0; k < KNN; ++k) g_ptopi[pb + k] = ti[k];
        }
    }
}

// ============================================================================
// Kernel 2b: exact fp32 rescore of 64 candidates -> top-16 + softmax gates.
// 1 block/token, 1 warp/head, 2 candidates per lane, warp-parallel ranking.
// ============================================================================
__global__ void __launch_bounds__(128) rescore_kernel(const float* __restrict__ keys)
{
    const int t = blockIdx.x;
    const int h = threadIdx.x >> 5;
    const int lane = threadIdx.x & 31;
    const int bh = t * H_HEADS + h;

    __shared__ float sq[H_HEADS][KD];
    *(float4*)(&sq[h][lane * 4]) = *(const float4*)(g_qf + (size_t)t * QDIM + h * KD + lane * 4);
    __syncwarp();

    const int idx0 = g_ptopi[(size_t)bh * NCAND + lane];
    const int idx1 = g_ptopi[(size_t)bh * NCAND + 32 + lane];
    const float4* kr0 = (const float4*)(keys + ((size_t)h * N_KEYS + idx0) * KD);
    const float4* kr1 = (const float4*)(keys + ((size_t)h * N_KEYS + idx1) * KD);
    float acc0 = 0.f, acc1 = 0.f;
#pragma unroll
    for (int d4 = 0; d4 < KD / 4; ++d4) {
        float4 k0 = kr0[d4], k1 = kr1[d4];
        float q0 = sq[h][4 * d4 + 0], q1 = sq[h][4 * d4 + 1];
        float q2 = sq[h][4 * d4 + 2], q3 = sq[h][4 * d4 + 3];
        acc0 = fmaf(k0.x, q0, acc0); acc0 = fmaf(k0.y, q1, acc0);
        acc0 = fmaf(k0.z, q2, acc0); acc0 = fmaf(k0.w, q3, acc0);
        acc1 = fmaf(k1.x, q0, acc1); acc1 = fmaf(k1.y, q1, acc1);
        acc1 = fmaf(k1.z, q2, acc1); acc1 = fmaf(k1.w, q3, acc1);
    }

    // rank among 64 candidates: order by (value desc, candidate-id asc)
    int rank0 = 0, rank1 = 0;
#pragma unroll
    for (int j = 0; j < 32; ++j) {
        float v0 = __shfl_sync(0xffffffffu, acc0, j);   // cand id j
        float v1 = __shfl_sync(0xffffffffu, acc1, j);   // cand id j+32
        rank0 += (v0 > acc0) || (v0 == acc0 && j < lane);
        rank0 += (v1 > acc0);                            // id j+32 > lane always -> no tie credit
        rank0 -= (v1 == acc0) ? 1 : 0;                   // tie with higher id: not counted
        rank0 += (v1 == acc0) ? 1 : 0;                   // (net 0; keep explicit)
        rank1 += (v0 > acc1) || (v0 == acc1);            // lower-half id always < id of acc1
        rank1 += (v1 > acc1) || (v1 == acc1 && j < lane);
    }
    // fix: v1 ties vs acc0 must NOT count (id j+32 > lane). Net effect above is 0. OK.

    float vmax = fmaxf(acc0, acc1);
#pragma unroll
    for (int off = 16; off > 0; off >>= 1)
        vmax = fmaxf(vmax, __shfl_xor_sync(0xffffffffu, vmax, off));
    float e0 = (rank0 < KNN) ? __expf(acc0 - vmax) : 0.f;
    float e1 = (rank1 < KNN) ? __expf(acc1 - vmax) : 0.f;
    float sum = e0 + e1;
#pragma unroll
    for (int off = 16; off > 0; off >>= 1)
        sum += __shfl_xor_sync(0xffffffffu, sum, off);
    float inv = 1.f / sum;
    if (rank0 < KNN) {
        g_gates[(size_t)bh * KNN + rank0]  = e0 * inv;
        g_topidx[(size_t)bh * KNN + rank0] = idx0;
    }
    if (rank1 < KNN) {
        g_gates[(size_t)bh * KNN + rank1]  = e1 * inv;
        g_topidx[(size_t)bh * KNN + rank1] = idx1;
    }
}

// ============================================================================
// Kernel 3: tiny PEER expert network per token (unchanged)
// ============================================================================
__global__ void moe_small_kernel(const float* __restrict__ x,
                                 const float* __restrict__ wdown,
                                 const float* __restrict__ wup,
                                 const float* __restrict__ aw1,
                                 const float* __restrict__ aw2,
                                 const float* __restrict__ aw3)
{
    __shared__ float s_aw1[HID_A * KNN];
    __shared__ float s_aw3[HID_A * KNN];
    __shared__ float s_aw2[KNN * HID_A];
    __shared__ float s_z[H_HEADS][KNN];
    __shared__ float s_hid[H_HEADS][HID_A];
    __shared__ float s_red[H_HEADS];
    __shared__ float s_wred[4];
    __shared__ float s_xsum;

    const int t = blockIdx.x;
    const int tid = threadIdx.x;
    const int w = tid >> 5;
    const int lane = tid & 31;

    for (int i = tid; i < HID_A * KNN; i += 128) { s_aw1[i] = aw1[i]; s_aw3[i] = aw3[i]; s_aw2[i] = aw2[i]; }

    float ps = 0.f;
    for (int i = tid; i < D_DIM; i += 128) ps += x[(size_t)t * D_DIM + i];
#pragma unroll
    for (int off = 16; off > 0; off >>= 1) ps += __shfl_down_sync(0xffffffffu, ps, off);
    if (lane == 0) s_wred[w] = ps;
    __syncthreads();
    if (tid == 0) s_xsum = s_wred[0] + s_wred[1] + s_wred[2] + s_wred[3];
    __syncthreads();
    const float xsum = s_xsum;

    const size_t gbase = ((size_t)t * H_HEADS + w) * KNN;
    if (lane < KNN)
        s_z[w][lane] = xsum * wdown[g_topidx[gbase + lane]];
    __syncwarp();

    for (int a = lane; a < HID_A; a += 32) {
        float d1 = 0.f, d3 = 0.f;
#pragma unroll
        for (int k = 0; k < KNN; ++k) {
            float zz = s_z[w][k];
            d1 = fmaf(zz, s_aw1[a * KNN + k], d1);
            d3 = fmaf(zz, s_aw3[a * KNN + k], d3);
        }
        float sl = d1 / (1.f + __expf(-d1));
        s_hid[w][a] = sl * d3;
    }
    __syncwarp();

    float part = 0.f;
    if (lane < KNN) {
        float o = 0.f;
#pragma unroll
        for (int a = 0; a < HID_A; ++a) o = fmaf(s_hid[w][a], s_aw2[lane * HID_A + a], o);
        int id = g_topidx[gbase + lane];
        part = o * g_gates[gbase + lane] * wup[id];
    }
#pragma unroll
    for (int off = 16; off > 0; off >>= 1) part += __shfl_down_sync(0xffffffffu, part, off);
    if (lane == 0) s_red[w] = part;
    __syncthreads();
    if (tid == 0) g_comb[t] = s_red[0] + s_red[1] + s_red[2] + s_red[3];
}

// ============================================================================
// Kernel 4: swiglu via HMMA 3-term split (unchanged from R8)
// ============================================================================
#define DW_AH 0
#define DW_AL 34816
#define DW_B  69632
#define DW_BSZ 17408
#define DW_TOTAL (DW_B + 4*DW_BSZ)   // 139264

__global__ void __launch_bounds__(256, 1) swiglu_mma_kernel()
{
    extern __shared__ char smem[];
    const uint32_t smb = smem_u32(smem);
    const int tid  = threadIdx.x;
    const int wid  = tid >> 5;
    const int lane = tid & 31;
    const int m0 = blockIdx.x * 128;
    const int n0 = blockIdx.y * 64;

    const int warp_m = wid >> 1;
    const int warp_n = wid & 1;

    const uint32_t a_row_off = (uint32_t)((warp_m * 32 + (lane & 15)) * AB_STRIDE + (lane >> 4) * 16);
    const uint32_t b_row_off = (uint32_t)((warp_n * 32 + (lane & 7) + ((lane >> 4) << 3)) * AB_STRIDE
                                          + ((lane >> 3) & 1) * 16);

    float C1[2][4][4] = {};
    float C3[2][4][4] = {};

    const char* axh = (const char*)(g_xhi + (size_t)m0 * D_DIM);
    const char* axl = (const char*)(g_xlo + (size_t)m0 * D_DIM);
    const char* b1h = (const char*)(g_w1hi + (size_t)n0 * D_DIM);
    const char* b1l = (const char*)(g_w1lo + (size_t)n0 * D_DIM);
    const char* b3h = (const char*)(g_w3hi + (size_t)n0 * D_DIM);
    const char* b3l = (const char*)(g_w3lo + (size_t)n0 * D_DIM);

    for (int kc = 0; kc < D_DIM / 128; ++kc) {
        if (kc) __syncthreads();
        const uint32_t ko = (uint32_t)(kc * 256);
#pragma unroll
        for (int it = 0; it < 8; ++it) {
            int idx = tid + it * 256;
            int r = idx >> 4, seg = idx & 15;
            uint32_t d = (uint32_t)(r * AB_STRIDE + seg * 16);
            uint32_t s = (uint32_t)(r * (D_DIM * 2)) + ko + seg * 16;
            CP_ASYNC16(smb + DW_AH + d, axh + s);
            CP_ASYNC16(smb + DW_AL + d, axl + s);
        }
#pragma unroll
        for (int it = 0; it < 4; ++it) {
            int idx = tid + it * 256;
            int r = idx >> 4, seg = idx & 15;
            uint32_t d = (uint32_t)(r * AB_STRIDE + seg * 16);
            uint32_t s = (uint32_t)(r * (D_DIM * 2)) + ko + seg * 16;
            CP_ASYNC16(smb + DW_B + 0 * DW_BSZ + d, b1h + s);
            CP_ASYNC16(smb + DW_B + 1 * DW_BSZ + d, b1l + s);
            CP_ASYNC16(smb + DW_B + 2 * DW_BSZ + d, b3h + s);
            CP_ASYNC16(smb + DW_B + 3 * DW_BSZ + d, b3l + s);
        }
        CP_COMMIT(); CP_WAIT0();
        __syncthreads();

#pragma unroll
        for (int ks = 0; ks < 8; ++ks) {
            const uint32_t koff = (uint32_t)(ks * 32);
            uint32_t b1H[8], b1L[8], b3H[8], b3L[8];
            ldmx4(b1H[0], b1H[1], b1H[2], b1H[3], smb + DW_B + 0 * DW_BSZ + b_row_off + koff);
            ldmx4(b1H[4], b1H[5], b1H[6], b1H[7], smb + DW_B + 0 * DW_BSZ + b_row_off + koff + 16 * AB_STRIDE);
            ldmx4(b1L[0], b1L[1], b1L[2], b1L[3], smb + DW_B + 1 * DW_BSZ + b_row_off + koff);
            ldmx4(b1L[4], b1L[5], b1L[6], b1L[7], smb + DW_B + 1 * DW_BSZ + b_row_off + koff + 16 * AB_STRIDE);
            ldmx4(b3H[0], b3H[1], b3H[2], b3H[3], smb + DW_B + 2 * DW_BSZ + b_row_off + koff);
            ldmx4(b3H[4], b3H[5], b3H[6], b3H[7], smb + DW_B + 2 * DW_BSZ + b_row_off + koff + 16 * AB_STRIDE);
            ldmx4(b3L[0], b3L[1], b3L[2], b3L[3], smb + DW_B + 3 * DW_BSZ + b_row_off + koff);
            ldmx4(b3L[4], b3L[5], b3L[6], b3L[7], smb + DW_B + 3 * DW_BSZ + b_row_off + koff + 16 * AB_STRIDE);
#pragma unroll
            for (int i = 0; i < 2; ++i) {
                uint32_t ah[4], al[4];
                ldmx4(ah[0], ah[1], ah[2], ah[3],
                      smb + DW_AH + a_row_off + koff + (uint32_t)(i * 16 * AB_STRIDE));
                ldmx4(al[0], al[1], al[2], al[3],
                      smb + DW_AL + a_row_off + koff + (uint32_t)(i * 16 * AB_STRIDE));
#pragma unroll
                for (int j = 0; j < 4; ++j) {
                    mma_bf16(C1[i][j], ah, b1H + 2 * j);
                    mma_bf16(C1[i][j], ah, b1L + 2 * j);
                    mma_bf16(C1[i][j], al, b1H + 2 * j);
                    mma_bf16(C3[i][j], ah, b3H + 2 * j);
                    mma_bf16(C3[i][j], ah, b3L + 2 * j);
                    mma_bf16(C3[i][j], al, b3H + 2 * j);
                }
            }
        }
    }

    const int trow = lane >> 2;
    const int tcol = (lane & 3) * 2;
#pragma unroll
    for (int i = 0; i < 2; ++i) {
#pragma unroll
        for (int j = 0; j < 4; ++j) {
            int n = n0 + warp_n * 32 + j * 8 + tcol;
#pragma unroll
            for (int half = 0; half < 2; ++half) {
                int m = m0 + warp_m * 32 + i * 16 + trow + half * 8;
                float z1a = C1[i][j][2 * half], z1b = C1[i][j][2 * half + 1];
                float z3a = C3[i][j][2 * half], z3b = C3[i][j][2 * half + 1];
                float va = (z1a / (1.f + __expf(-z1a))) * z3a;
                float vb = (z1b / (1.f + __expf(-z1b))) * z3b;
                __nv_bfloat16 ha = __float2bfloat16(va);
                __nv_bfloat16 hb = __float2bfloat16(vb);
                __nv_bfloat16 la = __float2bfloat16(va - __bfloat162float(ha));
                __nv_bfloat16 lb = __float2bfloat16(vb - __bfloat162float(hb));
                *(__nv_bfloat162*)(g_hidhi + (size_t)m * HID_S + n) = __nv_bfloat162(ha, hb);
                *(__nv_bfloat162*)(g_hidlo + (size_t)m * HID_S + n) = __nv_bfloat162(la, lb);
            }
        }
    }
}

// ============================================================================
// Kernel 5: out = hid @ w2^T + comb (unchanged from R8)
// ============================================================================
__global__ void __launch_bounds__(256, 1) out_mma_kernel(float* __restrict__ out)
{
    extern __shared__ char smem[];
    const uint32_t smb = smem_u32(smem);
    const int tid  = threadIdx.x;
    const int wid  = tid >> 5;
    const int lane = tid & 31;
    const int m0 = blockIdx.x * 128;
    const int n0 = blockIdx.y * 64;

    const int warp_m = wid >> 1;
    const int warp_n = wid & 1;

    const uint32_t a_row_off = (uint32_t)((warp_m * 32 + (lane & 15)) * AB_STRIDE + (lane >> 4) * 16);
    const uint32_t b_row_off = (uint32_t)((warp_n * 32 + (lane & 7) + ((lane >> 4) << 3)) * AB_STRIDE
                                          + ((lane >> 3) & 1) * 16);

    float C[2][4][4] = {};

    const char* axh = (const char*)(g_hidhi + (size_t)m0 * HID_S);
    const char* axl = (const char*)(g_hidlo + (size_t)m0 * HID_S);
    const char* bh_ = (const char*)(g_w2hi + (size_t)n0 * HID_S);
    const char* bl_ = (const char*)(g_w2lo + (size_t)n0 * HID_S);

    for (int kc = 0; kc < HID_S / 128; ++kc) {
        if (kc) __syncthreads();
        const uint32_t ko = (uint32_t)(kc * 256);
#pragma unroll
        for (int it = 0; it < 8; ++it) {
            int idx = tid + it * 256;
            int r = idx >> 4, seg = idx & 15;
            uint32_t d = (uint32_t)(r * AB_STRIDE + seg * 16);
            uint32_t s = (uint32_t)(r * (HID_S * 2)) + ko + seg * 16;
            CP_ASYNC16(smb + DO_AH + d, axh + s);
            CP_ASYNC16(smb + DO_AL + d, axl + s);
        }
#pragma unroll
        for (int it = 0; it < 4; ++it) {
            int idx = tid + it * 256;
            int r = idx >> 4, seg = idx & 15;
            uint32_t d = (uint32_t)(r * AB_STRIDE + seg * 16);
            uint32_t s = (uint32_t)(r * (HID_S * 2)) + ko + seg * 16;
            CP_ASYNC16(smb + DO_BH + d, bh_ + s);
            CP_ASYNC16(smb + DO_BL + d, bl_ + s);
        }
        CP_COMMIT(); CP_WAIT0();
        __syncthreads();

#pragma unroll
        for (int ks = 0; ks < 8; ++ks) {
            const uint32_t koff = (uint32_t)(ks * 32);
            uint32_t bH[8], bL[8];
            ldmx4(bH[0], bH[1], bH[2], bH[3], smb + DO_BH + b_row_off + koff);
            ldmx4(bH[4], bH[5], bH[6], bH[7], smb + DO_BH + b_row_off + koff + 16 * AB_STRIDE);
            ldmx4(bL[0], bL[1], bL[2], bL[3], smb + DO_BL + b_row_off + koff);
            ldmx4(bL[4], bL[5], bL[6], bL[7], smb + DO_BL + b_row_off + koff + 16 * AB_STRIDE);
#pragma unroll
            for (int i = 0; i < 2; ++i) {
                uint32_t ah[4], al[4];
                ldmx4(ah[0], ah[1], ah[2], ah[3],
                      smb + DO_AH + a_row_off + koff + (uint32_t)(i * 16 * AB_STRIDE));
                ldmx4(al[0], al[1], al[2], al[3],
                      smb + DO_AL + a_row_off + koff + (uint32_t)(i * 16 * AB_STRIDE));
#pragma unroll
                for (int j = 0; j < 4; ++j) {
                    mma_bf16(C[i][j], ah, bH + 2 * j);
                    mma_bf16(C[i][j], ah, bL + 2 * j);
                    mma_bf16(C[i][j], al, bH + 2 * j);
                }
            }
        }
    }

    const int trow = lane >> 2;
    const int tcol = (lane & 3) * 2;
#pragma unroll
    for (int i = 0; i < 2; ++i) {
#pragma unroll
        for (int half = 0; half < 2; ++half) {
            int m = m0 + warp_m * 32 + i * 16 + trow + half * 8;
            float cb = g_comb[m];
#pragma unroll
            for (int j = 0; j < 4; ++j) {
                int n = n0 + warp_n * 32 + j * 8 + tcol;
                *(float2*)(out + (size_t)m * D_DIM + n) =
                    make_float2(C[i][j][2 * half] + cb, C[i][j][2 * half + 1] + cb);
            }
        }
    }
}

// ============================================================================
extern "C" void kernel_launch(void* const* d_in, const int* in_sizes, int n_in,
                              void* d_out, int out_size)
{
    const float* x        = (const float*)d_in[0];
    const float* wq       = (const float*)d_in[1];
    const float* bq       = (const float*)d_in[2];
    const float* bn_gamma = (const float*)d_in[3];
    const float* bn_beta  = (const float*)d_in[4];
    const float* bn_mean  = (const float*)d_in[5];
    const float* bn_var   = (const float*)d_in[6];
    const float* keys     = (const float*)d_in[7];
    const float* w_down   = (const float*)d_in[8];
    const float* w_up     = (const float*)d_in[9];
    const float* a_w1     = (const float*)d_in[10];
    const float* a_w2     = (const float*)d_in[11];
    const float* a_w3     = (const float*)d_in[12];
    const float* s_w1     = (const float*)d_in[13];
    const float* s_w2     = (const float*)d_in[14];
    const float* s_w3     = (const float*)d_in[15];
    float* out            = (float*)d_out;

    __nv_bfloat16 *xhi, *xlo, *w1hi, *w1lo, *w3hi, *w3lo, *w2hi, *w2lo, *wqhi, *wqlo;
    cudaGetSymbolAddress((void**)&xhi, g_xhi);   cudaGetSymbolAddress((void**)&xlo, g_xlo);
    cudaGetSymbolAddress((void**)&w1hi, g_w1hi); cudaGetSymbolAddress((void**)&w1lo, g_w1lo);
    cudaGetSymbolAddress((void**)&w3hi, g_w3hi); cudaGetSymbolAddress((void**)&w3lo, g_w3lo);
    cudaGetSymbolAddress((void**)&w2hi, g_w2hi); cudaGetSymbolAddress((void**)&w2lo, g_w2lo);
    cudaGetSymbolAddress((void**)&wqhi, g_wqhi); cudaGetSymbolAddress((void**)&wqlo, g_wqlo);

    cudaFuncSetAttribute(scores_mma_kernel,
                         cudaFuncAttributeMaxDynamicSharedMemorySize, SMS_TOTAL);
    cudaFuncSetAttribute(qproj_mma_kernel,
                         cudaFuncAttributeMaxDynamicSharedMemorySize, DO_TOTAL);
    cudaFuncSetAttribute(swiglu_mma_kernel,
                         cudaFuncAttributeMaxDynamicSharedMemorySize, DW_TOTAL);
    cudaFuncSetAttribute(out_mma_kernel,
                         cudaFuncAttributeMaxDynamicSharedMemorySize, DO_TOTAL);

    keysprep_kernel<<<(H_HEADS * N_KEYS * KD) / (256 * 4), 256>>>(keys);
    split_kernel<<<(T_TOK * D_DIM / 4 + 255) / 256, 256>>>(x, xhi, xlo, T_TOK * D_DIM / 4);
    split_kernel<<<(QDIM * D_DIM / 4 + 255) / 256, 256>>>(wq, wqhi, wqlo, QDIM * D_DIM / 4);
    split_kernel<<<(HID_S * D_DIM / 4 + 255) / 256, 256>>>(s_w1, w1hi, w1lo, HID_S * D_DIM / 4);
    split_kernel<<<(HID_S * D_DIM / 4 + 255) / 256, 256>>>(s_w3, w3hi, w3lo, HID_S * D_DIM / 4);
    split_kernel<<<(D_DIM * HID_S / 4 + 255) / 256, 256>>>(s_w2, w2hi, w2lo, D_DIM * HID_S / 4);
    bnprep_kernel<<<(QDIM + 255) / 256, 256>>>(bq, bn_gamma, bn_beta, bn_mean, bn_var);
    qproj_mma_kernel<<<dim3(T_TOK / 128, QDIM / 64), 256, DO_TOTAL>>>();
    scores_mma_kernel<<<dim3(T_TOK / TOK_TILE, H_HEADS, KEY_SPLITS), 256, SMS_TOTAL>>>();
    rescore_kernel<<<T_TOK, 128>>>(keys);
    moe_small_kernel<<<T_TOK, 128>>>(x, w_down, w_up, a_w1, a_w2, a_w3);
    swiglu_mma_kernel<<<dim3(T_TOK / 128, HID_S / 64), 256, DW_TOTAL>>>();
    out_mma_kernel<<<dim3(T_TOK / 128, D_DIM / 64), 256, DO_TOTAL>>>(out);
}

// round 10
// speedup vs baseline: 2.7305x; 1.0010x over previous
#include <cuda_runtime.h>
#include <cuda_bf16.h>
#include <cfloat>
#include <math.h>
#include <cstdint>

#define T_TOK   2048
#define D_DIM   768
#define H_HEADS 4
#define N_KEYS  25600
#define KD      128
#define KNN     16
#define HID_A   44
#define HID_S   1024
#define QDIM    (H_HEADS*KD)   // 512
#define BN_EPS  1e-5f

#define KEY_SPLITS 4
#define KEYS_PER_SPLIT (N_KEYS / KEY_SPLITS)   // 6400
#define CHUNK_N 64
#define NCHUNK (KEYS_PER_SPLIT / CHUNK_N)      // 100
#define TOK_TILE 128
#define NCAND  (KEY_SPLITS * KNN)              // 64 candidates per (token, head)

// ---------------- scratch (device globals; no allocations allowed) ----------
__device__ __nv_bfloat16 g_qhi[T_TOK * QDIM];
__device__ float g_qf[T_TOK * QDIM];
__device__ __nv_bfloat16 g_khi[H_HEADS * N_KEYS * KD];
__device__ int   g_ptopi[T_TOK * H_HEADS * NCAND];
__device__ int   g_topidx[T_TOK * H_HEADS * KNN];
__device__ float g_gates[T_TOK * H_HEADS * KNN];
__device__ float g_comb[T_TOK];
__device__ float g_bnA[QDIM];
__device__ float g_bnB[QDIM];
// bf16 hi/lo operand splits
__device__ __nv_bfloat16 g_xhi[T_TOK * D_DIM];
__device__ __nv_bfloat16 g_xlo[T_TOK * D_DIM];
__device__ __nv_bfloat16 g_wqhi[QDIM * D_DIM];
__device__ __nv_bfloat16 g_wqlo[QDIM * D_DIM];
__device__ __nv_bfloat16 g_w1hi[HID_S * D_DIM];
__device__ __nv_bfloat16 g_w1lo[HID_S * D_DIM];
__device__ __nv_bfloat16 g_w3hi[HID_S * D_DIM];
__device__ __nv_bfloat16 g_w3lo[HID_S * D_DIM];
__device__ __nv_bfloat16 g_w2hi[D_DIM * HID_S];
__device__ __nv_bfloat16 g_w2lo[D_DIM * HID_S];
__device__ __nv_bfloat16 g_hidhi[T_TOK * HID_S];
__device__ __nv_bfloat16 g_hidlo[T_TOK * HID_S];

// ============================================================================
// helpers
// ============================================================================
__device__ __forceinline__ uint32_t smem_u32(const void* p) {
    uint32_t a;
    asm("{ .reg .u64 t; cvta.to.shared.u64 t, %1; cvt.u32.u64 %0, t; }" : "=r"(a) : "l"(p));
    return a;
}
#define CP_ASYNC16(dst, src) \
    asm volatile("cp.async.cg.shared.global [%0], [%1], 16;" :: "r"((uint32_t)(dst)), "l"(src))
#define CP_COMMIT() asm volatile("cp.async.commit_group;" ::: "memory")
#define CP_WAIT0()  asm volatile("cp.async.wait_group 0;" ::: "memory")

__device__ __forceinline__ void ldmx4(uint32_t& r0, uint32_t& r1, uint32_t& r2, uint32_t& r3,
                                      uint32_t addr) {
    asm volatile("ldmatrix.sync.aligned.m8n8.x4.shared.b16 {%0,%1,%2,%3}, [%4];"
                 : "=r"(r0), "=r"(r1), "=r"(r2), "=r"(r3) : "r"(addr));
}
__device__ __forceinline__ void mma_bf16(float* c, const uint32_t* a, const uint32_t* b) {
    asm volatile(
        "mma.sync.aligned.m16n8k16.row.col.f32.bf16.bf16.f32 "
        "{%0,%1,%2,%3}, {%4,%5,%6,%7}, {%8,%9}, {%0,%1,%2,%3};"
        : "+f"(c[0]), "+f"(c[1]), "+f"(c[2]), "+f"(c[3])
        : "r"(a[0]), "r"(a[1]), "r"(a[2]), "r"(a[3]), "r"(b[0]), "r"(b[1]));
}

// fully unrolled register insertion into sorted-desc list of 16
__device__ __forceinline__ void reg_insert16(float* tv, int* ti, float vv, int idx) {
#pragma unroll
    for (int p = KNN - 1; p > 0; --p) {
        bool shift = tv[p - 1] < vv;
        bool here  = !shift && (tv[p] < vv);
        float ntv = shift ? tv[p - 1] : (here ? vv : tv[p]);
        int   nti = shift ? ti[p - 1] : (here ? idx : ti[p]);
        tv[p] = ntv; ti[p] = nti;
    }
    if (tv[0] < vv) { tv[0] = vv; ti[0] = idx; }
}

// ============================================================================
// keysprep: fp32 keys -> bf16 hi
// ============================================================================
__global__ void keysprep_kernel(const float* __restrict__ keys)
{
    size_t i = (size_t)blockIdx.x * 256 + threadIdx.x;
    const float4 v = ((const float4*)keys)[i];
    ((__nv_bfloat162*)g_khi)[2 * i] =
        __nv_bfloat162(__float2bfloat16(v.x), __float2bfloat16(v.y));
    ((__nv_bfloat162*)g_khi)[2 * i + 1] =
        __nv_bfloat162(__float2bfloat16(v.z), __float2bfloat16(v.w));
}

// ============================================================================
// split: fp32 -> bf16 hi + lo residual
// ============================================================================
__global__ void split_kernel(const float* __restrict__ src,
                             __nv_bfloat16* __restrict__ hi,
                             __nv_bfloat16* __restrict__ lo, int n4)
{
    int i = blockIdx.x * 256 + threadIdx.x;
    if (i >= n4) return;
    float4 v = ((const float4*)src)[i];
    float f[4] = {v.x, v.y, v.z, v.w};
    __nv_bfloat16 h[4], l[4];
#pragma unroll
    for (int k = 0; k < 4; ++k) {
        h[k] = __float2bfloat16(f[k]);
        l[k] = __float2bfloat16(f[k] - __bfloat162float(h[k]));
    }
    ((__nv_bfloat162*)hi)[2 * i]     = __nv_bfloat162(h[0], h[1]);
    ((__nv_bfloat162*)hi)[2 * i + 1] = __nv_bfloat162(h[2], h[3]);
    ((__nv_bfloat162*)lo)[2 * i]     = __nv_bfloat162(l[0], l[1]);
    ((__nv_bfloat162*)lo)[2 * i + 1] = __nv_bfloat162(l[2], l[3]);
}

// ============================================================================
// bnprep: fused BN scale/shift per output column
// ============================================================================
__global__ void bnprep_kernel(const float* __restrict__ bq,
                              const float* __restrict__ gamma,
                              const float* __restrict__ beta,
                              const float* __restrict__ mean,
                              const float* __restrict__ var)
{
    int n = blockIdx.x * 256 + threadIdx.x;
    if (n >= QDIM) return;
    float sc = gamma[n] * rsqrtf(var[n] + BN_EPS);
    g_bnA[n] = sc;
    g_bnB[n] = (bq[n] - mean[n]) * sc + beta[n];
}

// ============================================================================
#define AB_STRIDE 272

// ============================================================================
// Kernel 1: qproj via HMMA 4-term split (hi*hi + hi*lo + lo*hi + lo*lo).
// ============================================================================
#define DO_AH 0
#define DO_AL 34816
#define DO_BH 69632
#define DO_BL (69632 + 17408)
#define DO_TOTAL (69632 + 2*17408)   // 104448

__global__ void __launch_bounds__(256, 2) qproj_mma_kernel()
{
    extern __shared__ char smem[];
    const uint32_t smb = smem_u32(smem);
    const int tid  = threadIdx.x;
    const int wid  = tid >> 5;
    const int lane = tid & 31;
    const int m0 = blockIdx.x * 128;
    const int n0 = blockIdx.y * 64;

    const int warp_m = wid >> 1;
    const int warp_n = wid & 1;

    const uint32_t a_row_off = (uint32_t)((warp_m * 32 + (lane & 15)) * AB_STRIDE + (lane >> 4) * 16);
    const uint32_t b_row_off = (uint32_t)((warp_n * 32 + (lane & 7) + ((lane >> 4) << 3)) * AB_STRIDE
                                          + ((lane >> 3) & 1) * 16);

    float C[2][4][4] = {};

    const char* axh = (const char*)(g_xhi + (size_t)m0 * D_DIM);
    const char* axl = (const char*)(g_xlo + (size_t)m0 * D_DIM);
    const char* bh_ = (const char*)(g_wqhi + (size_t)n0 * D_DIM);
    const char* bl_ = (const char*)(g_wqlo + (size_t)n0 * D_DIM);

    for (int kc = 0; kc < D_DIM / 128; ++kc) {
        if (kc) __syncthreads();
        const uint32_t ko = (uint32_t)(kc * 256);
#pragma unroll
        for (int it = 0; it < 8; ++it) {
            int idx = tid + it * 256;
            int r = idx >> 4, seg = idx & 15;
            uint32_t d = (uint32_t)(r * AB_STRIDE + seg * 16);
            uint32_t s = (uint32_t)(r * (D_DIM * 2)) + ko + seg * 16;
            CP_ASYNC16(smb + DO_AH + d, axh + s);
            CP_ASYNC16(smb + DO_AL + d, axl + s);
        }
#pragma unroll
        for (int it = 0; it < 4; ++it) {
            int idx = tid + it * 256;
            int r = idx >> 4, seg = idx & 15;
            uint32_t d = (uint32_t)(r * AB_STRIDE + seg * 16);
            uint32_t s = (uint32_t)(r * (D_DIM * 2)) + ko + seg * 16;
            CP_ASYNC16(smb + DO_BH + d, bh_ + s);
            CP_ASYNC16(smb + DO_BL + d, bl_ + s);
        }
        CP_COMMIT(); CP_WAIT0();
        __syncthreads();

#pragma unroll
        for (int ks = 0; ks < 8; ++ks) {
            const uint32_t koff = (uint32_t)(ks * 32);
            uint32_t bH[8], bL[8];
            ldmx4(bH[0], bH[1], bH[2], bH[3], smb + DO_BH + b_row_off + koff);
            ldmx4(bH[4], bH[5], bH[6], bH[7], smb + DO_BH + b_row_off + koff + 16 * AB_STRIDE);
            ldmx4(bL[0], bL[1], bL[2], bL[3], smb + DO_BL + b_row_off + koff);
            ldmx4(bL[4], bL[5], bL[6], bL[7], smb + DO_BL + b_row_off + koff + 16 * AB_STRIDE);
#pragma unroll
            for (int i = 0; i < 2; ++i) {
                uint32_t ah[4], al[4];
                ldmx4(ah[0], ah[1], ah[2], ah[3],
                      smb + DO_AH + a_row_off + koff + (uint32_t)(i * 16 * AB_STRIDE));
                ldmx4(al[0], al[1], al[2], al[3],
                      smb + DO_AL + a_row_off + koff + (uint32_t)(i * 16 * AB_STRIDE));
#pragma unroll
                for (int j = 0; j < 4; ++j) {
                    mma_bf16(C[i][j], ah, bH + 2 * j);
                    mma_bf16(C[i][j], ah, bL + 2 * j);
                    mma_bf16(C[i][j], al, bH + 2 * j);
                    mma_bf16(C[i][j], al, bL + 2 * j);
                }
            }
        }
    }

    const int trow = lane >> 2;
    const int tcol = (lane & 3) * 2;
#pragma unroll
    for (int i = 0; i < 2; ++i) {
#pragma unroll
        for (int half = 0; half < 2; ++half) {
            int m = m0 + warp_m * 32 + i * 16 + trow + half * 8;
#pragma unroll
            for (int j = 0; j < 4; ++j) {
                int n = n0 + warp_n * 32 + j * 8 + tcol;
                float va = C[i][j][2 * half]     * g_bnA[n]     + g_bnB[n];
                float vb = C[i][j][2 * half + 1] * g_bnA[n + 1] + g_bnB[n + 1];
                *(float2*)(g_qf + (size_t)m * QDIM + n) = make_float2(va, vb);
                *(__nv_bfloat162*)(g_qhi + (size_t)m * QDIM + n) =
                    __nv_bfloat162(__float2bfloat16(va), __float2bfloat16(vb));
            }
        }
    }
}

// ============================================================================
// Kernel 2: pass-1 scores, bf16-hi HMMA, 2 CTAs/SM.
// Prefetch hoisted above MMA for full-loop overlap.
// ============================================================================
#define SMS_A     0
#define SMS_B0    34816
#define SMS_B1    52224
#define SMS_S     69632
#define SMS_TOTAL 104448
#define S_STRIDE  68

__global__ void __launch_bounds__(256, 2) scores_mma_kernel()
{
    extern __shared__ char smem[];
    const uint32_t smb = smem_u32(smem);
    const int tid  = threadIdx.x;
    const int wid  = tid >> 5;
    const int lane = tid & 31;

    const int t0 = blockIdx.x * TOK_TILE;
    const int h  = blockIdx.y;
    const int z  = blockIdx.z;
    const int keybase = z * KEYS_PER_SPLIT;

    const int warp_m = wid >> 1;
    const int warp_n = wid & 1;

    uint32_t bdst[4], bsrc[4];
#pragma unroll
    for (int i = 0; i < 4; ++i) {
        int idx = tid + i * 256;
        int r = idx >> 4, seg = idx & 15;
        bdst[i] = (uint32_t)(r * AB_STRIDE + seg * 16);
        bsrc[i] = (uint32_t)(r * 256 + seg * 16);
    }

    {
        const char* qh = (const char*)(g_qhi + (size_t)t0 * QDIM + h * KD);
#pragma unroll
        for (int i = 0; i < 8; ++i) {
            int idx = tid + i * 256;
            int r = idx >> 4, seg = idx & 15;
            CP_ASYNC16(smb + SMS_A + (uint32_t)(r * AB_STRIDE + seg * 16),
                       qh + (size_t)r * (QDIM * 2) + seg * 16);
        }
    }
    const char* khbase = (const char*)(g_khi + ((size_t)h * N_KEYS + keybase) * KD);
    {
#pragma unroll
        for (int i = 0; i < 4; ++i) CP_ASYNC16(smb + SMS_B0 + bdst[i], khbase + bsrc[i]);
        CP_COMMIT();
    }

    float tv[KNN]; int ti[KNN];
#pragma unroll
    for (int k = 0; k < KNN; ++k) { tv[k] = -FLT_MAX; ti[k] = 0; }
    float minv = -FLT_MAX;

    const uint32_t a_row_off = (uint32_t)((warp_m * 32 + (lane & 15)) * AB_STRIDE + (lane >> 4) * 16);
    const uint32_t b_row_off = (uint32_t)((warp_n * 32 + (lane & 7) + ((lane >> 4) << 3)) * AB_STRIDE
                                          + ((lane >> 3) & 1) * 16);

    float* sS = (float*)(smem + SMS_S);
    const int s_token = tid >> 1;
    const int s_par   = tid & 1;

    for (int c = 0; c < NCHUNK; ++c) {
        const uint32_t bbase = (c & 1) ? (smb + SMS_B1) : (smb + SMS_B0);
        CP_WAIT0();
        __syncthreads();          // B(c) visible; scan of c-1 done by all

        // prefetch c+1 FIRST: its buffer's last reader (MMA c-1) is globally
        // complete at this point, and the load now overlaps the whole MMA(c).
        if (c + 1 < NCHUNK) {
            const uint32_t obase = (c & 1) ? (smb + SMS_B0) : (smb + SMS_B1);
            const uint32_t cb = (uint32_t)((c + 1) * CHUNK_N * KD * 2);
#pragma unroll
            for (int i = 0; i < 4; ++i) CP_ASYNC16(obase + bdst[i], khbase + cb + bsrc[i]);
            CP_COMMIT();
        }

        float C[2][4][4];
#pragma unroll
        for (int i = 0; i < 2; ++i)
#pragma unroll
            for (int j = 0; j < 4; ++j)
#pragma unroll
                for (int e = 0; e < 4; ++e) C[i][j][e] = 0.f;

#pragma unroll
        for (int ks = 0; ks < 8; ++ks) {
            const uint32_t koff = (uint32_t)(ks * 32);
            uint32_t bh[8];
            ldmx4(bh[0], bh[1], bh[2], bh[3], bbase + b_row_off + koff);
            ldmx4(bh[4], bh[5], bh[6], bh[7], bbase + b_row_off + koff + 16 * AB_STRIDE);
#pragma unroll
            for (int i = 0; i < 2; ++i) {
                uint32_t ah[4];
                ldmx4(ah[0], ah[1], ah[2], ah[3],
                      smb + SMS_A + a_row_off + koff + (uint32_t)(i * 16 * AB_STRIDE));
#pragma unroll
                for (int j = 0; j < 4; ++j) mma_bf16(C[i][j], ah, bh + 2 * j);
            }
        }

        // write scores
        const int trow = lane >> 2;
        const int tcol = (lane & 3) * 2;
#pragma unroll
        for (int i = 0; i < 2; ++i) {
            int tok = warp_m * 32 + i * 16 + trow;
#pragma unroll
            for (int j = 0; j < 4; ++j) {
                int key = warp_n * 32 + j * 8 + tcol;
                *(float2*)(sS + (size_t)tok * S_STRIDE + key)       = make_float2(C[i][j][0], C[i][j][1]);
                *(float2*)(sS + (size_t)(tok + 8) * S_STRIDE + key) = make_float2(C[i][j][2], C[i][j][3]);
            }
        }
        __syncthreads();

        // candidate scan: 2 threads per token
        {
            const float4* row = (const float4*)(sS + (size_t)s_token * S_STRIDE);
            const int n0 = keybase + c * CHUNK_N;
#pragma unroll 4
            for (int m = 0; m < 8; ++m) {
                int j4 = 2 * m + s_par;
                float4 v = row[j4];
                int base = n0 + 4 * j4;
                if (v.x > minv) { reg_insert16(tv, ti, v.x, base + 0); minv = tv[KNN - 1]; }
                if (v.y > minv) { reg_insert16(tv, ti, v.y, base + 1); minv = tv[KNN - 1]; }
                if (v.z > minv) { reg_insert16(tv, ti, v.z, base + 2); minv = tv[KNN - 1]; }
                if (v.w > minv) { reg_insert16(tv, ti, v.w, base + 3); minv = tv[KNN - 1]; }
            }
        }
    }

    // pair-merge the 2 streams per token via shfl
    {
        float ov[KNN]; int oi[KNN];
#pragma unroll
        for (int k = 0; k < KNN; ++k) {
            ov[k] = __shfl_down_sync(0xffffffffu, tv[k], 1);
            oi[k] = __shfl_down_sync(0xffffffffu, ti[k], 1);
        }
        if ((tid & 1) == 0) {
#pragma unroll
            for (int k = 0; k < KNN; ++k)
                if (ov[k] > tv[KNN - 1]) reg_insert16(tv, ti, ov[k], oi[k]);
            size_t pb = (((size_t)(t0 + (tid >> 1)) * H_HEADS + h) * KEY_SPLITS + z) * KNN;
#pragma unroll
            for (int k = 0; k < KNN; ++k) g_ptopi[pb + k] = ti[k];
        }
    }
}

// ============================================================================
// Kernel 2b: exact fp32 rescore of 64 candidates (unchanged)
// ============================================================================
__global__ void __launch_bounds__(128) rescore_kernel(const float* __restrict__ keys)
{
    const int t = blockIdx.x;
    const int h = threadIdx.x >> 5;
    const int lane = threadIdx.x & 31;
    const int bh = t * H_HEADS + h;

    __shared__ float sq[H_HEADS][KD];
    *(float4*)(&sq[h][lane * 4]) = *(const float4*)(g_qf + (size_t)t * QDIM + h * KD + lane * 4);
    __syncwarp();

    const int idx0 = g_ptopi[(size_t)bh * NCAND + lane];
    const int idx1 = g_ptopi[(size_t)bh * NCAND + 32 + lane];
    const float4* kr0 = (const float4*)(keys + ((size_t)h * N_KEYS + idx0) * KD);
    const float4* kr1 = (const float4*)(keys + ((size_t)h * N_KEYS + idx1) * KD);
    float acc0 = 0.f, acc1 = 0.f;
#pragma unroll
    for (int d4 = 0; d4 < KD / 4; ++d4) {
        float4 k0 = kr0[d4], k1 = kr1[d4];
        float q0 = sq[h][4 * d4 + 0], q1 = sq[h][4 * d4 + 1];
        float q2 = sq[h][4 * d4 + 2], q3 = sq[h][4 * d4 + 3];
        acc0 = fmaf(k0.x, q0, acc0); acc0 = fmaf(k0.y, q1, acc0);
        acc0 = fmaf(k0.z, q2, acc0); acc0 = fmaf(k0.w, q3, acc0);
        acc1 = fmaf(k1.x, q0, acc1); acc1 = fmaf(k1.y, q1, acc1);
        acc1 = fmaf(k1.z, q2, acc1); acc1 = fmaf(k1.w, q3, acc1);
    }

    int rank0 = 0, rank1 = 0;
#pragma unroll
    for (int j = 0; j < 32; ++j) {
        float v0 = __shfl_sync(0xffffffffu, acc0, j);
        float v1 = __shfl_sync(0xffffffffu, acc1, j);
        rank0 += (v0 > acc0) || (v0 == acc0 && j < lane);
        rank0 += (v1 > acc0);
        rank1 += (v0 > acc1) || (v0 == acc1);
        rank1 += (v1 > acc1) || (v1 == acc1 && j < lane);
    }

    float vmax = fmaxf(acc0, acc1);
#pragma unroll
    for (int off = 16; off > 0; off >>= 1)
        vmax = fmaxf(vmax, __shfl_xor_sync(0xffffffffu, vmax, off));
    float e0 = (rank0 < KNN) ? __expf(acc0 - vmax) : 0.f;
    float e1 = (rank1 < KNN) ? __expf(acc1 - vmax) : 0.f;
    float sum = e0 + e1;
#pragma unroll
    for (int off = 16; off > 0; off >>= 1)
        sum += __shfl_xor_sync(0xffffffffu, sum, off);
    float inv = 1.f / sum;
    if (rank0 < KNN) {
        g_gates[(size_t)bh * KNN + rank0]  = e0 * inv;
        g_topidx[(size_t)bh * KNN + rank0] = idx0;
    }
    if (rank1 < KNN) {
        g_gates[(size_t)bh * KNN + rank1]  = e1 * inv;
        g_topidx[(size_t)bh * KNN + rank1] = idx1;
    }
}

// ============================================================================
// Kernel 3: tiny PEER expert network per token (unchanged)
// ============================================================================
__global__ void moe_small_kernel(const float* __restrict__ x,
                                 const float* __restrict__ wdown,
                                 const float* __restrict__ wup,
                                 const float* __restrict__ aw1,
                                 const float* __restrict__ aw2,
                                 const float* __restrict__ aw3)
{
    __shared__ float s_aw1[HID_A * KNN];
    __shared__ float s_aw3[HID_A * KNN];
    __shared__ float s_aw2[KNN * HID_A];
    __shared__ float s_z[H_HEADS][KNN];
    __shared__ float s_hid[H_HEADS][HID_A];
    __shared__ float s_red[H_HEADS];
    __shared__ float s_wred[4];
    __shared__ float s_xsum;

    const int t = blockIdx.x;
    const int tid = threadIdx.x;
    const int w = tid >> 5;
    const int lane = tid & 31;

    for (int i = tid; i < HID_A * KNN; i += 128) { s_aw1[i] = aw1[i]; s_aw3[i] = aw3[i]; s_aw2[i] = aw2[i]; }

    float ps = 0.f;
    for (int i = tid; i < D_DIM; i += 128) ps += x[(size_t)t * D_DIM + i];
#pragma unroll
    for (int off = 16; off > 0; off >>= 1) ps += __shfl_down_sync(0xffffffffu, ps, off);
    if (lane == 0) s_wred[w] = ps;
    __syncthreads();
    if (tid == 0) s_xsum = s_wred[0] + s_wred[1] + s_wred[2] + s_wred[3];
    __syncthreads();
    const float xsum = s_xsum;

    const size_t gbase = ((size_t)t * H_HEADS + w) * KNN;
    if (lane < KNN)
        s_z[w][lane] = xsum * wdown[g_topidx[gbase + lane]];
    __syncwarp();

    for (int a = lane; a < HID_A; a += 32) {
        float d1 = 0.f, d3 = 0.f;
#pragma unroll
        for (int k = 0; k < KNN; ++k) {
            float zz = s_z[w][k];
            d1 = fmaf(zz, s_aw1[a * KNN + k], d1);
            d3 = fmaf(zz, s_aw3[a * KNN + k], d3);
        }
        float sl = d1 / (1.f + __expf(-d1));
        s_hid[w][a] = sl * d3;
    }
    __syncwarp();

    float part = 0.f;
    if (lane < KNN) {
        float o = 0.f;
#pragma unroll
        for (int a = 0; a < HID_A; ++a) o = fmaf(s_hid[w][a], s_aw2[lane * HID_A + a], o);
        int id = g_topidx[gbase + lane];
        part = o * g_gates[gbase + lane] * wup[id];
    }
#pragma unroll
    for (int off = 16; off > 0; off >>= 1) part += __shfl_down_sync(0xffffffffu, part, off);
    if (lane == 0) s_red[w] = part;
    __syncthreads();
    if (tid == 0) g_comb[t] = s_red[0] + s_red[1] + s_red[2] + s_red[3];
}

// ============================================================================
// Kernel 4: swiglu via HMMA 3-term split (unchanged)
// ============================================================================
#define DW_AH 0
#define DW_AL 34816
#define DW_B  69632
#define DW_BSZ 17408
#define DW_TOTAL (DW_B + 4*DW_BSZ)

__global__ void __launch_bounds__(256, 1) swiglu_mma_kernel()
{
    extern __shared__ char smem[];
    const uint32_t smb = smem_u32(smem);
    const int tid  = threadIdx.x;
    const int wid  = tid >> 5;
    const int lane = tid & 31;
    const int m0 = blockIdx.x * 128;
    const int n0 = blockIdx.y * 64;

    const int warp_m = wid >> 1;
    const int warp_n = wid & 1;

    const uint32_t a_row_off = (uint32_t)((warp_m * 32 + (lane & 15)) * AB_STRIDE + (lane >> 4) * 16);
    const uint32_t b_row_off = (uint32_t)((warp_n * 32 + (lane & 7) + ((lane >> 4) << 3)) * AB_STRIDE
                                          + ((lane >> 3) & 1) * 16);

    float C1[2][4][4] = {};
    float C3[2][4][4] = {};

    const char* axh = (const char*)(g_xhi + (size_t)m0 * D_DIM);
    const char* axl = (const char*)(g_xlo + (size_t)m0 * D_DIM);
    const char* b1h = (const char*)(g_w1hi + (size_t)n0 * D_DIM);
    const char* b1l = (const char*)(g_w1lo + (size_t)n0 * D_DIM);
    const char* b3h = (const char*)(g_w3hi + (size_t)n0 * D_DIM);
    const char* b3l = (const char*)(g_w3lo + (size_t)n0 * D_DIM);

    for (int kc = 0; kc < D_DIM / 128; ++kc) {
        if (kc) __syncthreads();
        const uint32_t ko = (uint32_t)(kc * 256);
#pragma unroll
        for (int it = 0; it < 8; ++it) {
            int idx = tid + it * 256;
            int r = idx >> 4, seg = idx & 15;
            uint32_t d = (uint32_t)(r * AB_STRIDE + seg * 16);
            uint32_t s = (uint32_t)(r * (D_DIM * 2)) + ko + seg * 16;
            CP_ASYNC16(smb + DW_AH + d, axh + s);
            CP_ASYNC16(smb + DW_AL + d, axl + s);
        }
#pragma unroll
        for (int it = 0; it < 4; ++it) {
            int idx = tid + it * 256;
            int r = idx >> 4, seg = idx & 15;
            uint32_t d = (uint32_t)(r * AB_STRIDE + seg * 16);
            uint32_t s = (uint32_t)(r * (D_DIM * 2)) + ko + seg * 16;
            CP_ASYNC16(smb + DW_B + 0 * DW_BSZ + d, b1h + s);
            CP_ASYNC16(smb + DW_B + 1 * DW_BSZ + d, b1l + s);
            CP_ASYNC16(smb + DW_B + 2 * DW_BSZ + d, b3h + s);
            CP_ASYNC16(smb + DW_B + 3 * DW_BSZ + d, b3l + s);
        }
        CP_COMMIT(); CP_WAIT0();
        __syncthreads();

#pragma unroll
        for (int ks = 0; ks < 8; ++ks) {
            const uint32_t koff = (uint32_t)(ks * 32);
            uint32_t b1H[8], b1L[8], b3H[8], b3L[8];
            ldmx4(b1H[0], b1H[1], b1H[2], b1H[3], smb + DW_B + 0 * DW_BSZ + b_row_off + koff);
            ldmx4(b1H[4], b1H[5], b1H[6], b1H[7], smb + DW_B + 0 * DW_BSZ + b_row_off + koff + 16 * AB_STRIDE);
            ldmx4(b1L[0], b1L[1], b1L[2], b1L[3], smb + DW_B + 1 * DW_BSZ + b_row_off + koff);
            ldmx4(b1L[4], b1L[5], b1L[6], b1L[7], smb + DW_B + 1 * DW_BSZ + b_row_off + koff + 16 * AB_STRIDE);
            ldmx4(b3H[0], b3H[1], b3H[2], b3H[3], smb + DW_B + 2 * DW_BSZ + b_row_off + koff);
            ldmx4(b3H[4], b3H[5], b3H[6], b3H[7], smb + DW_B + 2 * DW_BSZ + b_row_off + koff + 16 * AB_STRIDE);
            ldmx4(b3L[0], b3L[1], b3L[2], b3L[3], smb + DW_B + 3 * DW_BSZ + b_row_off + koff);
            ldmx4(b3L[4], b3L[5], b3L[6], b3L[7], smb + DW_B + 3 * DW_BSZ + b_row_off + koff + 16 * AB_STRIDE);
#pragma unroll
            for (int i = 0; i < 2; ++i) {
                uint32_t ah[4], al[4];
                ldmx4(ah[0], ah[1], ah[2], ah[3],
                      smb + DW_AH + a_row_off + koff + (uint32_t)(i * 16 * AB_STRIDE));
                ldmx4(al[0], al[1], al[2], al[3],
                      smb + DW_AL + a_row_off + koff + (uint32_t)(i * 16 * AB_STRIDE));
#pragma unroll
                for (int j = 0; j < 4; ++j) {
                    mma_bf16(C1[i][j], ah, b1H + 2 * j);
                    mma_bf16(C1[i][j], ah, b1L + 2 * j);
                    mma_bf16(C1[i][j], al, b1H + 2 * j);
                    mma_bf16(C3[i][j], ah, b3H + 2 * j);
                    mma_bf16(C3[i][j], ah, b3L + 2 * j);
                    mma_bf16(C3[i][j], al, b3H + 2 * j);
                }
            }
        }
    }

    const int trow = lane >> 2;
    const int tcol = (lane & 3) * 2;
#pragma unroll
    for (int i = 0; i < 2; ++i) {
#pragma unroll
        for (int j = 0; j < 4; ++j) {
            int n = n0 + warp_n * 32 + j * 8 + tcol;
#pragma unroll
            for (int half = 0; half < 2; ++half) {
                int m = m0 + warp_m * 32 + i * 16 + trow + half * 8;
                float z1a = C1[i][j][2 * half], z1b = C1[i][j][2 * half + 1];
                float z3a = C3[i][j][2 * half], z3b = C3[i][j][2 * half + 1];
                float va = (z1a / (1.f + __expf(-z1a))) * z3a;
                float vb = (z1b / (1.f + __expf(-z1b))) * z3b;
                __nv_bfloat16 ha = __float2bfloat16(va);
                __nv_bfloat16 hb = __float2bfloat16(vb);
                __nv_bfloat16 la = __float2bfloat16(va - __bfloat162float(ha));
                __nv_bfloat16 lb = __float2bfloat16(vb - __bfloat162float(hb));
                *(__nv_bfloat162*)(g_hidhi + (size_t)m * HID_S + n) = __nv_bfloat162(ha, hb);
                *(__nv_bfloat162*)(g_hidlo + (size_t)m * HID_S + n) = __nv_bfloat162(la, lb);
            }
        }
    }
}

// ============================================================================
// Kernel 5: out = hid @ w2^T + comb (unchanged)
// ============================================================================
__global__ void __launch_bounds__(256, 1) out_mma_kernel(float* __restrict__ out)
{
    extern __shared__ char smem[];
    const uint32_t smb = smem_u32(smem);
    const int tid  = threadIdx.x;
    const int wid  = tid >> 5;
    const int lane = tid & 31;
    const int m0 = blockIdx.x * 128;
    const int n0 = blockIdx.y * 64;

    const int warp_m = wid >> 1;
    const int warp_n = wid & 1;

    const uint32_t a_row_off = (uint32_t)((warp_m * 32 + (lane & 15)) * AB_STRIDE + (lane >> 4) * 16);
    const uint32_t b_row_off = (uint32_t)((warp_n * 32 + (lane & 7) + ((lane >> 4) << 3)) * AB_STRIDE
                                          + ((lane >> 3) & 1) * 16);

    float C[2][4][4] = {};

    const char* axh = (const char*)(g_hidhi + (size_t)m0 * HID_S);
    const char* axl = (const char*)(g_hidlo + (size_t)m0 * HID_S);
    const char* bh_ = (const char*)(g_w2hi + (size_t)n0 * HID_S);
    const char* bl_ = (const char*)(g_w2lo + (size_t)n0 * HID_S);

    for (int kc = 0; kc < HID_S / 128; ++kc) {
        if (kc) __syncthreads();
        const uint32_t ko = (uint32_t)(kc * 256);
#pragma unroll
        for (int it = 0; it < 8; ++it) {
            int idx = tid + it * 256;
            int r = idx >> 4, seg = idx & 15;
            uint32_t d = (uint32_t)(r * AB_STRIDE + seg * 16);
            uint32_t s = (uint32_t)(r * (HID_S * 2)) + ko + seg * 16;
            CP_ASYNC16(smb + DO_AH + d, axh + s);
            CP_ASYNC16(smb + DO_AL + d, axl + s);
        }
#pragma unroll
        for (int it = 0; it < 4; ++it) {
            int idx = tid + it * 256;
            int r = idx >> 4, seg = idx & 15;
            uint32_t d = (uint32_t)(r * AB_STRIDE + seg * 16);
            uint32_t s = (uint32_t)(r * (HID_S * 2)) + ko + seg * 16;
            CP_ASYNC16(smb + DO_BH + d, bh_ + s);
            CP_ASYNC16(smb + DO_BL + d, bl_ + s);
        }
        CP_COMMIT(); CP_WAIT0();
        __syncthreads();

#pragma unroll
        for (int ks = 0; ks < 8; ++ks) {
            const uint32_t koff = (uint32_t)(ks * 32);
            uint32_t bH[8], bL[8];
            ldmx4(bH[0], bH[1], bH[2], bH[3], smb + DO_BH + b_row_off + koff);
            ldmx4(bH[4], bH[5], bH[6], bH[7], smb + DO_BH + b_row_off + koff + 16 * AB_STRIDE);
            ldmx4(bL[0], bL[1], bL[2], bL[3], smb + DO_BL + b_row_off + koff);
            ldmx4(bL[4], bL[5], bL[6], bL[7], smb + DO_BL + b_row_off + koff + 16 * AB_STRIDE);
#pragma unroll
            for (int i = 0; i < 2; ++i) {
                uint32_t ah[4], al[4];
                ldmx4(ah[0], ah[1], ah[2], ah[3],
                      smb + DO_AH + a_row_off + koff + (uint32_t)(i * 16 * AB_STRIDE));
                ldmx4(al[0], al[1], al[2], al[3],
                      smb + DO_AL + a_row_off + koff + (uint32_t)(i * 16 * AB_STRIDE));
#pragma unroll
                for (int j = 0; j < 4; ++j) {
                    mma_bf16(C[i][j], ah, bH + 2 * j);
                    mma_bf16(C[i][j], ah, bL + 2 * j);
                    mma_bf16(C[i][j], al, bH + 2 * j);
                }
            }
        }
    }

    const int trow = lane >> 2;
    const int tcol = (lane & 3) * 2;
#pragma unroll
    for (int i = 0; i < 2; ++i) {
#pragma unroll
        for (int half = 0; half < 2; ++half) {
            int m = m0 + warp_m * 32 + i * 16 + trow + half * 8;
            float cb = g_comb[m];
#pragma unroll
            for (int j = 0; j < 4; ++j) {
                int n = n0 + warp_n * 32 + j * 8 + tcol;
                *(float2*)(out + (size_t)m * D_DIM + n) =
                    make_float2(C[i][j][2 * half] + cb, C[i][j][2 * half + 1] + cb);
            }
        }
    }
}

// ============================================================================
extern "C" void kernel_launch(void* const* d_in, const int* in_sizes, int n_in,
                              void* d_out, int out_size)
{
    const float* x        = (const float*)d_in[0];
    const float* wq       = (const float*)d_in[1];
    const float* bq       = (const float*)d_in[2];
    const float* bn_gamma = (const float*)d_in[3];
    const float* bn_beta  = (const float*)d_in[4];
    const float* bn_mean  = (const float*)d_in[5];
    const float* bn_var   = (const float*)d_in[6];
    const float* keys     = (const float*)d_in[7];
    const float* w_down   = (const float*)d_in[8];
    const float* w_up     = (const float*)d_in[9];
    const float* a_w1     = (const float*)d_in[10];
    const float* a_w2     = (const float*)d_in[11];
    const float* a_w3     = (const float*)d_in[12];
    const float* s_w1     = (const float*)d_in[13];
    const float* s_w2     = (const float*)d_in[14];
    const float* s_w3     = (const float*)d_in[15];
    float* out            = (float*)d_out;

    __nv_bfloat16 *xhi, *xlo, *w1hi, *w1lo, *w3hi, *w3lo, *w2hi, *w2lo, *wqhi, *wqlo;
    cudaGetSymbolAddress((void**)&xhi, g_xhi);   cudaGetSymbolAddress((void**)&xlo, g_xlo);
    cudaGetSymbolAddress((void**)&w1hi, g_w1hi); cudaGetSymbolAddress((void**)&w1lo, g_w1lo);
    cudaGetSymbolAddress((void**)&w3hi, g_w3hi); cudaGetSymbolAddress((void**)&w3lo, g_w3lo);
    cudaGetSymbolAddress((void**)&w2hi, g_w2hi); cudaGetSymbolAddress((void**)&w2lo, g_w2lo);
    cudaGetSymbolAddress((void**)&wqhi, g_wqhi); cudaGetSymbolAddress((void**)&wqlo, g_wqlo);

    cudaFuncSetAttribute(scores_mma_kernel,
                         cudaFuncAttributeMaxDynamicSharedMemorySize, SMS_TOTAL);
    cudaFuncSetAttribute(qproj_mma_kernel,
                         cudaFuncAttributeMaxDynamicSharedMemorySize, DO_TOTAL);
    cudaFuncSetAttribute(swiglu_mma_kernel,
                         cudaFuncAttributeMaxDynamicSharedMemorySize, DW_TOTAL);
    cudaFuncSetAttribute(out_mma_kernel,
                         cudaFuncAttributeMaxDynamicSharedMemorySize, DO_TOTAL);

    // launches 1-5 (so ncu -s 5 -c 1 captures scores_mma as launch 6)
    keysprep_kernel<<<(H_HEADS * N_KEYS * KD) / (256 * 4), 256>>>(keys);
    split_kernel<<<(T_TOK * D_DIM / 4 + 255) / 256, 256>>>(x, xhi, xlo, T_TOK * D_DIM / 4);
    split_kernel<<<(QDIM * D_DIM / 4 + 255) / 256, 256>>>(wq, wqhi, wqlo, QDIM * D_DIM / 4);
    bnprep_kernel<<<(QDIM + 255) / 256, 256>>>(bq, bn_gamma, bn_beta, bn_mean, bn_var);
    qproj_mma_kernel<<<dim3(T_TOK / 128, QDIM / 64), 256, DO_TOTAL>>>();
    // launch 6: the kernel we need profiled
    scores_mma_kernel<<<dim3(T_TOK / TOK_TILE, H_HEADS, KEY_SPLITS), 256, SMS_TOTAL>>>();
    // remaining prep + dependent kernels
    split_kernel<<<(HID_S * D_DIM / 4 + 255) / 256, 256>>>(s_w1, w1hi, w1lo, HID_S * D_DIM / 4);
    split_kernel<<<(HID_S * D_DIM / 4 + 255) / 256, 256>>>(s_w3, w3hi, w3lo, HID_S * D_DIM / 4);
    split_kernel<<<(D_DIM * HID_S / 4 + 255) / 256, 256>>>(s_w2, w2hi, w2lo, D_DIM * HID_S / 4);
    rescore_kernel<<<T_TOK, 128>>>(keys);
    moe_small_kernel<<<T_TOK, 128>>>(x, w_down, w_up, a_w1, a_w2, a_w3);
    swiglu_mma_kernel<<<dim3(T_TOK / 128, HID_S / 64), 256, DW_TOTAL>>>();
    out_mma_kernel<<<dim3(T_TOK / 128, D_DIM / 64), 256, DO_TOTAL>>>(out);
}